// round 13
// baseline (speedup 1.0000x reference)
#include <cuda_runtime.h>
#include <cuda_bf16.h>
#include <math.h>
#include <stdint.h>

// Problem constants
#define T_ 2048
#define B_ 2
#define D_ 768
#define H_ 8
#define HD_ 96
#define FFN_ 3072
#define NR_ (T_ * B_)          // 4096 rows
#define BH_ (B_ * H_)          // 16 attention batches

// ---------------- scratch ----------------
__device__ float g_tmp1[NR_ * D_];
__device__ float g_x1[NR_ * D_];
__device__ float g_y[NR_ * D_];

// bf16 hi/lo split buffers
__device__ __nv_bfloat16 g_xh[NR_ * D_],  g_xl[NR_ * D_];
__device__ __nv_bfloat16 g_qh[NR_ * D_],  g_ql[NR_ * D_];
__device__ __nv_bfloat16 g_kh[NR_ * D_],  g_kl[NR_ * D_];
__device__ __nv_bfloat16 g_vh[NR_ * D_],  g_vl[NR_ * D_];
__device__ __nv_bfloat16 g_ah[NR_ * D_],  g_al[NR_ * D_];
__device__ __nv_bfloat16 g_x1h[NR_ * D_], g_x1l[NR_ * D_];
__device__ __nv_bfloat16 g_h1h[NR_ * FFN_], g_h1l[NR_ * FFN_];
__device__ __nv_bfloat16 g_wqh[D_ * D_], g_wql[D_ * D_];
__device__ __nv_bfloat16 g_wkh[D_ * D_], g_wkl[D_ * D_];
__device__ __nv_bfloat16 g_wvh[D_ * D_], g_wvl[D_ * D_];
__device__ __nv_bfloat16 g_woh[D_ * D_], g_wol[D_ * D_];
__device__ __nv_bfloat16 g_w1h[FFN_ * D_], g_w1l[FFN_ * D_];
__device__ __nv_bfloat16 g_w2h[D_ * FFN_], g_w2l[D_ * FFN_];

// ================= helpers =================
__device__ __forceinline__ uint32_t pack2(__nv_bfloat16 a, __nv_bfloat16 b) {
    return (uint32_t)__bfloat16_as_ushort(a) | ((uint32_t)__bfloat16_as_ushort(b) << 16);
}
__device__ __forceinline__ void split2(float v, __nv_bfloat16& h, __nv_bfloat16& l) {
    h = __float2bfloat16(v);
    l = __float2bfloat16(v - __bfloat162float(h));
}
__device__ __forceinline__ void mma16816(float* c, const uint32_t* a, const uint32_t* b) {
    asm volatile(
        "mma.sync.aligned.m16n8k16.row.col.f32.bf16.bf16.f32 "
        "{%0,%1,%2,%3}, {%4,%5,%6,%7}, {%8,%9}, {%0,%1,%2,%3};"
        : "+f"(c[0]), "+f"(c[1]), "+f"(c[2]), "+f"(c[3])
        : "r"(a[0]), "r"(a[1]), "r"(a[2]), "r"(a[3]), "r"(b[0]), "r"(b[1]));
}
__device__ __forceinline__ uint32_t smaddr(const void* p) {
    return (uint32_t)__cvta_generic_to_shared(p);
}
#define CP16(dst, src) \
    asm volatile("cp.async.cg.shared.global [%0], [%1], 16;" :: "r"(dst), "l"(src))
#define CP_COMMIT() asm volatile("cp.async.commit_group;" ::: "memory")
#define CP_WAIT0()  asm volatile("cp.async.wait_group 0;" ::: "memory")

// ================= fused split kernel (7 regions, 1 launch) =================
// region blocks of 1024 elems: x:3072 | wq:576 | wk:576 | wv:576 | wo:576 | w1:2304 | w2:2304
#define SPLIT_BLOCKS 9984
__global__ void split_all(const float* __restrict__ x,
                          const float* __restrict__ wq, const float* __restrict__ wk,
                          const float* __restrict__ wv, const float* __restrict__ wo,
                          const float* __restrict__ w1, const float* __restrict__ w2,
                          __nv_bfloat16* xh, __nv_bfloat16* xl,
                          __nv_bfloat16* wqh, __nv_bfloat16* wql,
                          __nv_bfloat16* wkh, __nv_bfloat16* wkl,
                          __nv_bfloat16* wvh, __nv_bfloat16* wvl,
                          __nv_bfloat16* woh, __nv_bfloat16* wol,
                          __nv_bfloat16* w1h, __nv_bfloat16* w1l,
                          __nv_bfloat16* w2h, __nv_bfloat16* w2l)
{
    int bid = blockIdx.x;
    const float* in; __nv_bfloat16 *hi, *lo; int start;
    if      (bid < 3072) { in = x;  hi = xh;  lo = xl;  start = 0; }
    else if (bid < 3648) { in = wq; hi = wqh; lo = wql; start = 3072; }
    else if (bid < 4224) { in = wk; hi = wkh; lo = wkl; start = 3648; }
    else if (bid < 4800) { in = wv; hi = wvh; lo = wvl; start = 4224; }
    else if (bid < 5376) { in = wo; hi = woh; lo = wol; start = 4800; }
    else if (bid < 7680) { in = w1; hi = w1h; lo = w1l; start = 5376; }
    else                 { in = w2; hi = w2h; lo = w2l; start = 7680; }
    int i = (bid - start) * 1024 + threadIdx.x * 4;
    float4 v = *(const float4*)(in + i);
    __nv_bfloat16 h0, h1, h2, h3, l0, l1, l2, l3;
    split2(v.x, h0, l0); split2(v.y, h1, l1);
    split2(v.z, h2, l2); split2(v.w, h3, l3);
    *(uint2*)(hi + i) = make_uint2(pack2(h0, h1), pack2(h2, h3));
    *(uint2*)(lo + i) = make_uint2(pack2(l0, l1), pack2(l2, l3));
}

// ================= flash attention (R10 version — best measured) =================
// grid (T/64, BH); 128 threads; 4 warps x 16 Q rows; occ 2.
#define QP 104          // Q/K smem pitch (elems)
#define VP 72           // V^T smem pitch (elems)
#define SQH 0
#define SQL 6656
#define SKH 13312
#define SKL 19968
#define SVH 26624
#define SVL 33536
#define FLASH_SMEM (40448 * 2)

__global__ __launch_bounds__(128, 2)
void flash_attn(const __nv_bfloat16* __restrict__ Qh_g, const __nv_bfloat16* __restrict__ Ql_g,
                const __nv_bfloat16* __restrict__ Kh_g, const __nv_bfloat16* __restrict__ Kl_g,
                const __nv_bfloat16* __restrict__ Vh_g, const __nv_bfloat16* __restrict__ Vl_g,
                __nv_bfloat16* __restrict__ Oh_g, __nv_bfloat16* __restrict__ Ol_g,
                float scale2)
{
    extern __shared__ __nv_bfloat16 sm[];
    const int tid = threadIdx.x;
    const int lane = tid & 31;
    const int w = tid >> 5;
    const int rql = lane >> 2;
    const int kof = (lane & 3) << 1;
    const int q0 = blockIdx.x * 64;
    const int z = blockIdx.y;
    const int bb = z >> 3, hh = z & 7;
    const long base = (long)bb * D_ + (long)hh * HD_;
    const int ldr = B_ * D_;

    // ---- Q tile (64 x 96) hi/lo via cp.async
    {
        const int r = tid >> 1;
        const int c0 = (tid & 1) * 48;
        const __nv_bfloat16* sh = Qh_g + (long)(q0 + r) * ldr + base + c0;
        const __nv_bfloat16* sl = Ql_g + (long)(q0 + r) * ldr + base + c0;
        uint32_t dh = smaddr(sm + SQH + r * QP + c0);
        uint32_t dl = smaddr(sm + SQL + r * QP + c0);
#pragma unroll
        for (int j = 0; j < 6; j++) {
            CP16(dh + 16 * j, sh + 8 * j);
            CP16(dl + 16 * j, sl + 8 * j);
        }
        CP_COMMIT();
        CP_WAIT0();
    }
    __syncthreads();

    // ---- Q fragments to registers
    uint32_t Qfh[6][4], Qfl[6][4];
    {
        const int r0 = 16 * w + rql;
#pragma unroll
        for (int kb = 0; kb < 6; kb++) {
            const int kc = kb * 16 + kof;
            Qfh[kb][0] = *(const uint32_t*)(sm + SQH + r0 * QP + kc);
            Qfh[kb][1] = *(const uint32_t*)(sm + SQH + (r0 + 8) * QP + kc);
            Qfh[kb][2] = *(const uint32_t*)(sm + SQH + r0 * QP + kc + 8);
            Qfh[kb][3] = *(const uint32_t*)(sm + SQH + (r0 + 8) * QP + kc + 8);
            Qfl[kb][0] = *(const uint32_t*)(sm + SQL + r0 * QP + kc);
            Qfl[kb][1] = *(const uint32_t*)(sm + SQL + (r0 + 8) * QP + kc);
            Qfl[kb][2] = *(const uint32_t*)(sm + SQL + r0 * QP + kc + 8);
            Qfl[kb][3] = *(const uint32_t*)(sm + SQL + (r0 + 8) * QP + kc + 8);
        }
    }

    float O[12][4];
#pragma unroll
    for (int i = 0; i < 12; i++)
#pragma unroll
        for (int j = 0; j < 4; j++) O[i][j] = 0.f;
    float mrow[2] = {-1e30f, -1e30f};
    float lrow[2] = {0.f, 0.f};

    for (int s0 = 0; s0 < T_; s0 += 64) {
        __syncthreads();
        // ---- K tile hi/lo via cp.async
        {
            const int r = tid >> 1;
            const int c0 = (tid & 1) * 48;
            const __nv_bfloat16* sh = Kh_g + (long)(s0 + r) * ldr + base + c0;
            const __nv_bfloat16* sl = Kl_g + (long)(s0 + r) * ldr + base + c0;
            uint32_t dh = smaddr(sm + SKH + r * QP + c0);
            uint32_t dl = smaddr(sm + SKL + r * QP + c0);
#pragma unroll
            for (int j = 0; j < 6; j++) {
                CP16(dh + 16 * j, sh + 8 * j);
                CP16(dl + 16 * j, sl + 8 * j);
            }
            CP_COMMIT();
        }
        // ---- V tile -> transposed split smem [dim][key] (overlaps K cp.async)
        {
            const int r = (w & 1) * 32 + lane;
            const int c0 = (w >> 1) * 48;
            const __nv_bfloat16* sh = Vh_g + (long)(s0 + r) * ldr + base + c0;
            const __nv_bfloat16* sl = Vl_g + (long)(s0 + r) * ldr + base + c0;
#pragma unroll
            for (int j = 0; j < 6; j++) {
                uint4 vh = *(const uint4*)(sh + 8 * j);
                uint4 vl = *(const uint4*)(sl + 8 * j);
                const ushort* ph = (const ushort*)&vh;
                const ushort* pl = (const ushort*)&vl;
#pragma unroll
                for (int u = 0; u < 8; u++) {
                    sm[SVH + (c0 + 8 * j + u) * VP + r] = __ushort_as_bfloat16(ph[u]);
                    sm[SVL + (c0 + 8 * j + u) * VP + r] = __ushort_as_bfloat16(pl[u]);
                }
            }
        }
        CP_WAIT0();
        __syncthreads();

        // ---- S = Q K^T  (kb outer, nt-block 4, term-major: chain dist 4)
        float S[8][4];
#pragma unroll
        for (int nt = 0; nt < 8; nt++) {
            S[nt][0] = S[nt][1] = S[nt][2] = S[nt][3] = 0.f;
        }
#pragma unroll
        for (int kb = 0; kb < 6; kb++) {
            const int kc = kb * 16 + kof;
#pragma unroll
            for (int nb = 0; nb < 8; nb += 4) {
                uint32_t bh[4][2], bl[4][2];
#pragma unroll
                for (int j = 0; j < 4; j++) {
                    const int n0 = (nb + j) * 8 + rql;
                    bh[j][0] = *(const uint32_t*)(sm + SKH + n0 * QP + kc);
                    bh[j][1] = *(const uint32_t*)(sm + SKH + n0 * QP + kc + 8);
                    bl[j][0] = *(const uint32_t*)(sm + SKL + n0 * QP + kc);
                    bl[j][1] = *(const uint32_t*)(sm + SKL + n0 * QP + kc + 8);
                }
#pragma unroll
                for (int j = 0; j < 4; j++) mma16816(S[nb + j], Qfh[kb], bh[j]);
#pragma unroll
                for (int j = 0; j < 4; j++) mma16816(S[nb + j], Qfl[kb], bh[j]);
#pragma unroll
                for (int j = 0; j < 4; j++) mma16816(S[nb + j], Qfh[kb], bl[j]);
            }
        }

        // ---- base-2 online softmax
        float rmax0 = -1e30f, rmax1 = -1e30f;
#pragma unroll
        for (int nt = 0; nt < 8; nt++) {
            S[nt][0] *= scale2; S[nt][1] *= scale2;
            S[nt][2] *= scale2; S[nt][3] *= scale2;
            rmax0 = fmaxf(rmax0, fmaxf(S[nt][0], S[nt][1]));
            rmax1 = fmaxf(rmax1, fmaxf(S[nt][2], S[nt][3]));
        }
        rmax0 = fmaxf(rmax0, __shfl_xor_sync(0xffffffffu, rmax0, 1));
        rmax0 = fmaxf(rmax0, __shfl_xor_sync(0xffffffffu, rmax0, 2));
        rmax1 = fmaxf(rmax1, __shfl_xor_sync(0xffffffffu, rmax1, 1));
        rmax1 = fmaxf(rmax1, __shfl_xor_sync(0xffffffffu, rmax1, 2));

        const float m0n = fmaxf(mrow[0], rmax0);
        const float m1n = fmaxf(mrow[1], rmax1);
        const float a0 = exp2f(mrow[0] - m0n);
        const float a1 = exp2f(mrow[1] - m1n);
        mrow[0] = m0n; mrow[1] = m1n;

        float rs0 = 0.f, rs1 = 0.f;
#pragma unroll
        for (int nt = 0; nt < 8; nt++) {
            S[nt][0] = exp2f(S[nt][0] - m0n);
            S[nt][1] = exp2f(S[nt][1] - m0n);
            S[nt][2] = exp2f(S[nt][2] - m1n);
            S[nt][3] = exp2f(S[nt][3] - m1n);
            rs0 += S[nt][0] + S[nt][1];
            rs1 += S[nt][2] + S[nt][3];
        }
        rs0 += __shfl_xor_sync(0xffffffffu, rs0, 1);
        rs0 += __shfl_xor_sync(0xffffffffu, rs0, 2);
        rs1 += __shfl_xor_sync(0xffffffffu, rs1, 1);
        rs1 += __shfl_xor_sync(0xffffffffu, rs1, 2);
        lrow[0] = lrow[0] * a0 + rs0;
        lrow[1] = lrow[1] * a1 + rs1;

#pragma unroll
        for (int i = 0; i < 12; i++) {
            O[i][0] *= a0; O[i][1] *= a0;
            O[i][2] *= a1; O[i][3] *= a1;
        }

        // ---- P -> hi/lo A-fragments
        uint32_t Ph[4][4], Pl[4][4];
#pragma unroll
        for (int kb = 0; kb < 4; kb++) {
            const float* s0f = S[2 * kb];
            const float* s1f = S[2 * kb + 1];
            __nv_bfloat16 h00,h01,h02,h03,h10,h11,h12,h13;
            __nv_bfloat16 l00,l01,l02,l03,l10,l11,l12,l13;
            split2(s0f[0],h00,l00); split2(s0f[1],h01,l01);
            split2(s0f[2],h02,l02); split2(s0f[3],h03,l03);
            split2(s1f[0],h10,l10); split2(s1f[1],h11,l11);
            split2(s1f[2],h12,l12); split2(s1f[3],h13,l13);
            Ph[kb][0] = pack2(h00, h01); Ph[kb][1] = pack2(h02, h03);
            Ph[kb][2] = pack2(h10, h11); Ph[kb][3] = pack2(h12, h13);
            Pl[kb][0] = pack2(l00, l01); Pl[kb][1] = pack2(l02, l03);
            Pl[kb][2] = pack2(l10, l11); Pl[kb][3] = pack2(l12, l13);
        }

        // ---- O += P @ V^T  (kb outer, nt-block 4, term-major: chain dist 4)
#pragma unroll
        for (int kb = 0; kb < 4; kb++) {
            const int kc = kb * 16 + kof;
#pragma unroll
            for (int nb = 0; nb < 12; nb += 4) {
                uint32_t bh[4][2], bl[4][2];
#pragma unroll
                for (int j = 0; j < 4; j++) {
                    const int n0 = (nb + j) * 8 + rql;
                    bh[j][0] = *(const uint32_t*)(sm + SVH + n0 * VP + kc);
                    bh[j][1] = *(const uint32_t*)(sm + SVH + n0 * VP + kc + 8);
                    bl[j][0] = *(const uint32_t*)(sm + SVL + n0 * VP + kc);
                    bl[j][1] = *(const uint32_t*)(sm + SVL + n0 * VP + kc + 8);
                }
#pragma unroll
                for (int j = 0; j < 4; j++) mma16816(O[nb + j], Ph[kb], bh[j]);
#pragma unroll
                for (int j = 0; j < 4; j++) mma16816(O[nb + j], Pl[kb], bh[j]);
#pragma unroll
                for (int j = 0; j < 4; j++) mma16816(O[nb + j], Ph[kb], bl[j]);
            }
        }
    }

    // ---- epilogue: normalize, split, write hi/lo
    const float inv0 = 1.f / lrow[0];
    const float inv1 = 1.f / lrow[1];
    const int r0 = q0 + 16 * w + rql;
#pragma unroll
    for (int nt = 0; nt < 12; nt++) {
        const int cb = nt * 8 + kof;
        const long o0 = (long)r0 * ldr + base + cb;
        const long o1 = (long)(r0 + 8) * ldr + base + cb;
        __nv_bfloat16 h0,h1,h2,h3,l0,l1,l2,l3;
        split2(O[nt][0] * inv0, h0, l0);
        split2(O[nt][1] * inv0, h1, l1);
        split2(O[nt][2] * inv1, h2, l2);
        split2(O[nt][3] * inv1, h3, l3);
        *(uint32_t*)(Oh_g + o0) = pack2(h0, h1);
        *(uint32_t*)(Ol_g + o0) = pack2(l0, l1);
        *(uint32_t*)(Oh_g + o1) = pack2(h2, h3);
        *(uint32_t*)(Ol_g + o1) = pack2(l2, l3);
    }
}

// ================= HMMA GEMM, pre-split bf16, cp.async, KC=64 =================
// Term-major MMA ordering (chain dist 16); 2 syncs per 64 K-elems (was per 32).
#define KC 64
#define PA 72                      // 64 cols + 8 pad; conflict-free (4-bank row stride)
#define TILE_E (128 * PA)          // 9216 elems per array
#define GEMM_SMEM (2 * 4 * TILE_E * 2)   // 147456 B

__device__ __forceinline__
void gemm_body(__nv_bfloat16* sm,
               const __nv_bfloat16* __restrict__ Ah, const __nv_bfloat16* __restrict__ Al,
               const __nv_bfloat16* __restrict__ Bh, const __nv_bfloat16* __restrict__ Bl,
               const float* __restrict__ bias, const float* __restrict__ residual,
               float* __restrict__ Cf,
               __nv_bfloat16* __restrict__ Ch, __nv_bfloat16* __restrict__ Cl,
               int K, int lda, int ldb, int ldc, int relu)
{
    const int tid = threadIdx.x;
    const int lane = tid & 31;
    const int wid = tid >> 5;
    const int warpM = wid >> 2;
    const int warpN = wid & 3;
    const int rowBase = blockIdx.y * 128;
    const int colBase = blockIdx.x * 128;

    const int r = tid >> 1;            // 0..127
    const int hf = (tid & 1) << 5;     // 0 or 32 elems (64B half-row)

    auto issue = [&](int k0, int buf) {
        __nv_bfloat16* pAh = sm + buf * 4 * TILE_E;
        const long aoff = (long)(rowBase + r) * lda + k0 + hf;
        const long boff = (long)(colBase + r) * ldb + k0 + hf;
        const uint32_t d = smaddr(&pAh[r * PA + hf]);
#pragma unroll
        for (int j = 0; j < 4; j++) {
            CP16(d + 16 * j,                   Ah + aoff + 8 * j);
            CP16(d + TILE_E * 2 + 16 * j,      Al + aoff + 8 * j);
            CP16(d + TILE_E * 4 + 16 * j,      Bh + boff + 8 * j);
            CP16(d + TILE_E * 6 + 16 * j,      Bl + boff + 8 * j);
        }
        CP_COMMIT();
    };

    float acc[4][4][4];
#pragma unroll
    for (int i = 0; i < 4; i++)
#pragma unroll
        for (int j = 0; j < 4; j++)
#pragma unroll
            for (int rr = 0; rr < 4; rr++) acc[i][j][rr] = 0.f;

    const int NC = K / KC;
    issue(0, 0);
    CP_WAIT0();
    __syncthreads();

    int buf = 0;
    for (int c = 0; c < NC; c++) {
        const bool has = (c + 1) < NC;
        if (has) issue((c + 1) * KC, buf ^ 1);

        const __nv_bfloat16* pAh = sm + buf * 4 * TILE_E;
        const __nv_bfloat16* pAl = pAh + TILE_E;
        const __nv_bfloat16* pBh = pAh + 2 * TILE_E;
        const __nv_bfloat16* pBl = pAh + 3 * TILE_E;
        const int rql = lane >> 2;
        const int kof = (lane & 3) << 1;

#pragma unroll
        for (int ks = 0; ks < KC; ks += 16) {
            const int kcol = ks + kof;
            uint32_t bh[4][2], bl[4][2];
#pragma unroll
            for (int nt = 0; nt < 4; nt++) {
                const int n0 = warpN * 32 + nt * 8 + rql;
                bh[nt][0] = *(const uint32_t*)&pBh[n0 * PA + kcol];
                bh[nt][1] = *(const uint32_t*)&pBh[n0 * PA + kcol + 8];
                bl[nt][0] = *(const uint32_t*)&pBl[n0 * PA + kcol];
                bl[nt][1] = *(const uint32_t*)&pBl[n0 * PA + kcol + 8];
            }
            uint32_t ah[4][4], al[4][4];
#pragma unroll
            for (int mt = 0; mt < 4; mt++) {
                const int r0 = warpM * 64 + mt * 16 + rql;
                ah[mt][0] = *(const uint32_t*)&pAh[r0 * PA + kcol];
                ah[mt][1] = *(const uint32_t*)&pAh[(r0 + 8) * PA + kcol];
                ah[mt][2] = *(const uint32_t*)&pAh[r0 * PA + kcol + 8];
                ah[mt][3] = *(const uint32_t*)&pAh[(r0 + 8) * PA + kcol + 8];
                al[mt][0] = *(const uint32_t*)&pAl[r0 * PA + kcol];
                al[mt][1] = *(const uint32_t*)&pAl[(r0 + 8) * PA + kcol];
                al[mt][2] = *(const uint32_t*)&pAl[r0 * PA + kcol + 8];
                al[mt][3] = *(const uint32_t*)&pAl[(r0 + 8) * PA + kcol + 8];
            }
            // term-major: 16 independent MMAs between accumulator reuses
#pragma unroll
            for (int mt = 0; mt < 4; mt++)
#pragma unroll
                for (int nt = 0; nt < 4; nt++)
                    mma16816(acc[mt][nt], ah[mt], bh[nt]);
#pragma unroll
            for (int mt = 0; mt < 4; mt++)
#pragma unroll
                for (int nt = 0; nt < 4; nt++)
                    mma16816(acc[mt][nt], al[mt], bh[nt]);
#pragma unroll
            for (int mt = 0; mt < 4; mt++)
#pragma unroll
                for (int nt = 0; nt < 4; nt++)
                    mma16816(acc[mt][nt], ah[mt], bl[nt]);
        }

        if (has) CP_WAIT0();
        __syncthreads();
        buf ^= 1;
    }

    const int rql = lane >> 2;
    const int cof = (lane & 3) << 1;
#pragma unroll
    for (int mt = 0; mt < 4; mt++) {
        const int r0 = rowBase + warpM * 64 + mt * 16 + rql;
#pragma unroll
        for (int nt = 0; nt < 4; nt++) {
            const int cb = colBase + warpN * 32 + nt * 8 + cof;
            float* a4 = acc[mt][nt];
            float2 bb = make_float2(0.f, 0.f);
            if (bias) bb = *(const float2*)(bias + cb);
            float v0 = a4[0] + bb.x;
            float v1 = a4[1] + bb.y;
            float v2 = a4[2] + bb.x;
            float v3 = a4[3] + bb.y;
            if (relu) {
                v0 = fmaxf(v0, 0.f); v1 = fmaxf(v1, 0.f);
                v2 = fmaxf(v2, 0.f); v3 = fmaxf(v3, 0.f);
            }
            const long o0 = (long)r0 * ldc + cb;
            const long o1 = (long)(r0 + 8) * ldc + cb;
            if (residual) {
                float2 r00 = *(const float2*)(residual + o0);
                float2 r11 = *(const float2*)(residual + o1);
                v0 += r00.x; v1 += r00.y; v2 += r11.x; v3 += r11.y;
            }
            if (Cf) {
                *(float2*)(Cf + o0) = make_float2(v0, v1);
                *(float2*)(Cf + o1) = make_float2(v2, v3);
            }
            if (Ch) {
                __nv_bfloat16 h0,h1,h2,h3,l0,l1,l2,l3;
                split2(v0, h0, l0); split2(v1, h1, l1);
                split2(v2, h2, l2); split2(v3, h3, l3);
                *(uint32_t*)(Ch + o0) = pack2(h0, h1);
                *(uint32_t*)(Cl + o0) = pack2(l0, l1);
                *(uint32_t*)(Ch + o1) = pack2(h2, h3);
                *(uint32_t*)(Cl + o1) = pack2(l2, l3);
            }
        }
    }
}

__global__ __launch_bounds__(256)
void gemm_hmma(const __nv_bfloat16* Ah, const __nv_bfloat16* Al,
               const __nv_bfloat16* Bh, const __nv_bfloat16* Bl,
               const float* bias, const float* residual,
               float* Cf, __nv_bfloat16* Ch, __nv_bfloat16* Cl,
               int K, int lda, int ldb, int ldc, int relu)
{
    extern __shared__ char dsm[];
    gemm_body((__nv_bfloat16*)dsm, Ah, Al, Bh, Bl, bias, residual,
              Cf, Ch, Cl, K, lda, ldb, ldc, relu);
}

// fused QKV: blockIdx.z selects weight/bias/output; emits split outputs
__global__ __launch_bounds__(256)
void gemm_qkv(const __nv_bfloat16* xh, const __nv_bfloat16* xl,
              const __nv_bfloat16* w0h, const __nv_bfloat16* w0l,
              const __nv_bfloat16* w1h, const __nv_bfloat16* w1l,
              const __nv_bfloat16* w2h, const __nv_bfloat16* w2l,
              const float* b0, const float* b1, const float* b2,
              __nv_bfloat16* c0h, __nv_bfloat16* c0l,
              __nv_bfloat16* c1h, __nv_bfloat16* c1l,
              __nv_bfloat16* c2h, __nv_bfloat16* c2l)
{
    extern __shared__ char dsm[];
    const int z = blockIdx.z;
    const __nv_bfloat16* Bh = (z == 0) ? w0h : (z == 1) ? w1h : w2h;
    const __nv_bfloat16* Bl = (z == 0) ? w0l : (z == 1) ? w1l : w2l;
    const float* bias = (z == 0) ? b0 : (z == 1) ? b1 : b2;
    __nv_bfloat16* Ch = (z == 0) ? c0h : (z == 1) ? c1h : c2h;
    __nv_bfloat16* Cl = (z == 0) ? c0l : (z == 1) ? c1l : c2l;
    gemm_body((__nv_bfloat16*)dsm, xh, xl, Bh, Bl, bias, nullptr,
              nullptr, Ch, Cl, D_, D_, D_, D_, 0);
}

// ---------------- block reduction ----------------
__device__ __forceinline__ float blockReduceSum(float v) {
    __shared__ float s[8];
#pragma unroll
    for (int o = 16; o > 0; o >>= 1) v += __shfl_xor_sync(0xffffffffu, v, o);
    int w = threadIdx.x >> 5, l = threadIdx.x & 31;
    if (l == 0) s[w] = v;
    __syncthreads();
    if (threadIdx.x < 32) {
        v = (threadIdx.x < 8) ? s[threadIdx.x] : 0.f;
#pragma unroll
        for (int o = 4; o > 0; o >>= 1) v += __shfl_xor_sync(0xffffffffu, v, o);
        if (threadIdx.x == 0) s[0] = v;
    }
    __syncthreads();
    v = s[0];
    __syncthreads();
    return v;
}

// ---------------- layernorm (optional split emit) ----------------
__global__ void layernorm_kernel(const float* __restrict__ X,
                                 const float* __restrict__ g,
                                 const float* __restrict__ b,
                                 float* __restrict__ Y,
                                 __nv_bfloat16* __restrict__ Yh,
                                 __nv_bfloat16* __restrict__ Yl) {
    long row = blockIdx.x;
    const float* p = X + row * D_;
    int tid = threadIdx.x;
    float vals[3];
    float sum = 0.f;
#pragma unroll
    for (int i = 0; i < 3; i++) {
        vals[i] = p[tid + i * 256];
        sum += vals[i];
    }
    float mu = blockReduceSum(sum) * (1.f / D_);
    float vs = 0.f;
#pragma unroll
    for (int i = 0; i < 3; i++) {
        float d = vals[i] - mu;
        vs += d * d;
    }
    float var = blockReduceSum(vs) * (1.f / D_);
    float rs = rsqrtf(var + 1e-5f);
#pragma unroll
    for (int i = 0; i < 3; i++) {
        int c = tid + i * 256;
        float o = (vals[i] - mu) * rs * g[c] + b[c];
        if (Y) Y[row * D_ + c] = o;
        if (Yh) {
            __nv_bfloat16 h, l;
            split2(o, h, l);
            Yh[row * D_ + c] = h;
            Yl[row * D_ + c] = l;
        }
    }
}

// ---------------- launch ----------------
extern "C" void kernel_launch(void* const* d_in, const int* in_sizes, int n_in,
                              void* d_out, int out_size)
{
    const float* x     = (const float*)d_in[0];
    const float* wq    = (const float*)d_in[1];
    const float* bq    = (const float*)d_in[2];
    const float* wk    = (const float*)d_in[3];
    const float* bk    = (const float*)d_in[4];
    const float* wv    = (const float*)d_in[5];
    const float* bv    = (const float*)d_in[6];
    const float* wo    = (const float*)d_in[7];
    const float* bo    = (const float*)d_in[8];
    const float* ln1g  = (const float*)d_in[9];
    const float* ln1b  = (const float*)d_in[10];
    const float* w1    = (const float*)d_in[11];
    const float* b1    = (const float*)d_in[12];
    const float* w2    = (const float*)d_in[13];
    const float* b2    = (const float*)d_in[14];
    const float* ln2g  = (const float*)d_in[15];
    const float* ln2b  = (const float*)d_in[16];
    float* out = (float*)d_out;

    float *tmp1, *x1, *y;
    cudaGetSymbolAddress((void**)&tmp1, g_tmp1);
    cudaGetSymbolAddress((void**)&x1,   g_x1);
    cudaGetSymbolAddress((void**)&y,    g_y);

    __nv_bfloat16 *xh,*xl,*qh,*ql,*kh,*kl,*vh,*vl,*ah,*al,*x1h,*x1l,*h1h,*h1l;
    __nv_bfloat16 *wqh,*wql,*wkh,*wkl,*wvh,*wvl,*woh,*wol,*w1h,*w1l,*w2h,*w2l;
    cudaGetSymbolAddress((void**)&xh, g_xh);   cudaGetSymbolAddress((void**)&xl, g_xl);
    cudaGetSymbolAddress((void**)&qh, g_qh);   cudaGetSymbolAddress((void**)&ql, g_ql);
    cudaGetSymbolAddress((void**)&kh, g_kh);   cudaGetSymbolAddress((void**)&kl, g_kl);
    cudaGetSymbolAddress((void**)&vh, g_vh);   cudaGetSymbolAddress((void**)&vl, g_vl);
    cudaGetSymbolAddress((void**)&ah, g_ah);   cudaGetSymbolAddress((void**)&al, g_al);
    cudaGetSymbolAddress((void**)&x1h, g_x1h); cudaGetSymbolAddress((void**)&x1l, g_x1l);
    cudaGetSymbolAddress((void**)&h1h, g_h1h); cudaGetSymbolAddress((void**)&h1l, g_h1l);
    cudaGetSymbolAddress((void**)&wqh, g_wqh); cudaGetSymbolAddress((void**)&wql, g_wql);
    cudaGetSymbolAddress((void**)&wkh, g_wkh); cudaGetSymbolAddress((void**)&wkl, g_wkl);
    cudaGetSymbolAddress((void**)&wvh, g_wvh); cudaGetSymbolAddress((void**)&wvl, g_wvl);
    cudaGetSymbolAddress((void**)&woh, g_woh); cudaGetSymbolAddress((void**)&wol, g_wol);
    cudaGetSymbolAddress((void**)&w1h, g_w1h); cudaGetSymbolAddress((void**)&w1l, g_w1l);
    cudaGetSymbolAddress((void**)&w2h, g_w2h); cudaGetSymbolAddress((void**)&w2l, g_w2l);

    cudaFuncSetAttribute(gemm_hmma, cudaFuncAttributeMaxDynamicSharedMemorySize, GEMM_SMEM);
    cudaFuncSetAttribute(gemm_qkv,  cudaFuncAttributeMaxDynamicSharedMemorySize, GEMM_SMEM);
    cudaFuncSetAttribute(flash_attn, cudaFuncAttributeMaxDynamicSharedMemorySize, FLASH_SMEM);

    const float scale2 = 0.102062072615966f * 1.44269504088896f;
    dim3 blk(256);

    // ---- one-time splits (x + all weights, single launch)
    split_all<<<SPLIT_BLOCKS, blk>>>(x, wq, wk, wv, wo, w1, w2,
                                     xh, xl, wqh, wql, wkh, wkl, wvh, wvl,
                                     woh, wol, w1h, w1l, w2h, w2l);

    // ---- QKV projections (fused; split outputs feed flash)
    dim3 gQKV(D_ / 128, NR_ / 128, 3);
    gemm_qkv<<<gQKV, blk, GEMM_SMEM>>>(xh, xl, wqh, wql, wkh, wkl, wvh, wvl,
                                       bq, bk, bv, qh, ql, kh, kl, vh, vl);

    // ---- flash attention (split in, split out)
    dim3 gFA(T_ / 64, BH_);
    flash_attn<<<gFA, dim3(128), FLASH_SMEM>>>(qh, ql, kh, kl, vh, vl, ah, al, scale2);

    // ---- O projection + residual(x) -> tmp1 (fp32)
    dim3 gProj(D_ / 128, NR_ / 128);
    gemm_hmma<<<gProj, blk, GEMM_SMEM>>>(ah, al, woh, wol, bo, x,
                                         tmp1, nullptr, nullptr, D_, D_, D_, D_, 0);

    // ---- LN1 -> x1 fp32 + split
    layernorm_kernel<<<NR_, blk>>>(tmp1, ln1g, ln1b, x1, x1h, x1l);

    // ---- FFN1: relu -> h1 split only
    dim3 gF1(FFN_ / 128, NR_ / 128);
    gemm_hmma<<<gF1, blk, GEMM_SMEM>>>(x1h, x1l, w1h, w1l, b1, nullptr,
                                       nullptr, h1h, h1l, D_, D_, D_, FFN_, 1);

    // ---- FFN2 + residual(x1) -> y fp32
    gemm_hmma<<<gProj, blk, GEMM_SMEM>>>(h1h, h1l, w2h, w2l, b2, x1,
                                         y, nullptr, nullptr, FFN_, FFN_, FFN_, D_, 0);

    // ---- LN2 -> out
    layernorm_kernel<<<NR_, blk>>>(y, ln2g, ln2b, out, nullptr, nullptr);
}

// round 16
// speedup vs baseline: 1.0997x; 1.0997x over previous
#include <cuda_runtime.h>
#include <cuda_bf16.h>
#include <math.h>
#include <stdint.h>

// Problem constants
#define T_ 2048
#define B_ 2
#define D_ 768
#define H_ 8
#define HD_ 96
#define FFN_ 3072
#define NR_ (T_ * B_)          // 4096 rows
#define BH_ (B_ * H_)          // 16 attention batches

// ---------------- scratch ----------------
__device__ float g_tmp1[NR_ * D_];
__device__ float g_x1[NR_ * D_];
__device__ float g_y[NR_ * D_];

// bf16 hi/lo split buffers
__device__ __nv_bfloat16 g_xh[NR_ * D_],  g_xl[NR_ * D_];
__device__ __nv_bfloat16 g_qh[NR_ * D_],  g_ql[NR_ * D_];
__device__ __nv_bfloat16 g_kh[NR_ * D_],  g_kl[NR_ * D_];
__device__ __nv_bfloat16 g_vh[NR_ * D_],  g_vl[NR_ * D_];
__device__ __nv_bfloat16 g_ah[NR_ * D_],  g_al[NR_ * D_];
__device__ __nv_bfloat16 g_x1h[NR_ * D_], g_x1l[NR_ * D_];
__device__ __nv_bfloat16 g_h1h[NR_ * FFN_], g_h1l[NR_ * FFN_];
__device__ __nv_bfloat16 g_wqh[D_ * D_], g_wql[D_ * D_];
__device__ __nv_bfloat16 g_wkh[D_ * D_], g_wkl[D_ * D_];
__device__ __nv_bfloat16 g_wvh[D_ * D_], g_wvl[D_ * D_];
__device__ __nv_bfloat16 g_woh[D_ * D_], g_wol[D_ * D_];
__device__ __nv_bfloat16 g_w1h[FFN_ * D_], g_w1l[FFN_ * D_];
__device__ __nv_bfloat16 g_w2h[D_ * FFN_], g_w2l[D_ * FFN_];

// ================= helpers =================
__device__ __forceinline__ uint32_t pack2(__nv_bfloat16 a, __nv_bfloat16 b) {
    return (uint32_t)__bfloat16_as_ushort(a) | ((uint32_t)__bfloat16_as_ushort(b) << 16);
}
__device__ __forceinline__ void split2(float v, __nv_bfloat16& h, __nv_bfloat16& l) {
    h = __float2bfloat16(v);
    l = __float2bfloat16(v - __bfloat162float(h));
}
__device__ __forceinline__ void mma16816(float* c, const uint32_t* a, const uint32_t* b) {
    asm volatile(
        "mma.sync.aligned.m16n8k16.row.col.f32.bf16.bf16.f32 "
        "{%0,%1,%2,%3}, {%4,%5,%6,%7}, {%8,%9}, {%0,%1,%2,%3};"
        : "+f"(c[0]), "+f"(c[1]), "+f"(c[2]), "+f"(c[3])
        : "r"(a[0]), "r"(a[1]), "r"(a[2]), "r"(a[3]), "r"(b[0]), "r"(b[1]));
}
__device__ __forceinline__ uint32_t smaddr(const void* p) {
    return (uint32_t)__cvta_generic_to_shared(p);
}
#define CP16(dst, src) \
    asm volatile("cp.async.cg.shared.global [%0], [%1], 16;" :: "r"(dst), "l"(src))
#define CP_COMMIT() asm volatile("cp.async.commit_group;" ::: "memory")
#define CP_WAIT0()  asm volatile("cp.async.wait_group 0;" ::: "memory")

// ================= fused split kernel (7 regions, 1 launch) =================
// region blocks of 1024 elems: x:3072 | wq:576 | wk:576 | wv:576 | wo:576 | w1:2304 | w2:2304
#define SPLIT_BLOCKS 9984
__global__ void split_all(const float* __restrict__ x,
                          const float* __restrict__ wq, const float* __restrict__ wk,
                          const float* __restrict__ wv, const float* __restrict__ wo,
                          const float* __restrict__ w1, const float* __restrict__ w2,
                          __nv_bfloat16* xh, __nv_bfloat16* xl,
                          __nv_bfloat16* wqh, __nv_bfloat16* wql,
                          __nv_bfloat16* wkh, __nv_bfloat16* wkl,
                          __nv_bfloat16* wvh, __nv_bfloat16* wvl,
                          __nv_bfloat16* woh, __nv_bfloat16* wol,
                          __nv_bfloat16* w1h, __nv_bfloat16* w1l,
                          __nv_bfloat16* w2h, __nv_bfloat16* w2l)
{
    int bid = blockIdx.x;
    const float* in; __nv_bfloat16 *hi, *lo; int start;
    if      (bid < 3072) { in = x;  hi = xh;  lo = xl;  start = 0; }
    else if (bid < 3648) { in = wq; hi = wqh; lo = wql; start = 3072; }
    else if (bid < 4224) { in = wk; hi = wkh; lo = wkl; start = 3648; }
    else if (bid < 4800) { in = wv; hi = wvh; lo = wvl; start = 4224; }
    else if (bid < 5376) { in = wo; hi = woh; lo = wol; start = 4800; }
    else if (bid < 7680) { in = w1; hi = w1h; lo = w1l; start = 5376; }
    else                 { in = w2; hi = w2h; lo = w2l; start = 7680; }
    int i = (bid - start) * 1024 + threadIdx.x * 4;
    float4 v = *(const float4*)(in + i);
    __nv_bfloat16 h0, h1, h2, h3, l0, l1, l2, l3;
    split2(v.x, h0, l0); split2(v.y, h1, l1);
    split2(v.z, h2, l2); split2(v.w, h3, l3);
    *(uint2*)(hi + i) = make_uint2(pack2(h0, h1), pack2(h2, h3));
    *(uint2*)(lo + i) = make_uint2(pack2(l0, l1), pack2(l2, l3));
}

// ================= flash attention (R10 version — best measured) =================
// grid (T/64, BH); 128 threads; 4 warps x 16 Q rows; occ 2.
#define QP 104          // Q/K smem pitch (elems)
#define VP 72           // V^T smem pitch (elems)
#define SQH 0
#define SQL 6656
#define SKH 13312
#define SKL 19968
#define SVH 26624
#define SVL 33536
#define FLASH_SMEM (40448 * 2)

__global__ __launch_bounds__(128, 2)
void flash_attn(const __nv_bfloat16* __restrict__ Qh_g, const __nv_bfloat16* __restrict__ Ql_g,
                const __nv_bfloat16* __restrict__ Kh_g, const __nv_bfloat16* __restrict__ Kl_g,
                const __nv_bfloat16* __restrict__ Vh_g, const __nv_bfloat16* __restrict__ Vl_g,
                __nv_bfloat16* __restrict__ Oh_g, __nv_bfloat16* __restrict__ Ol_g,
                float scale2)
{
    extern __shared__ __nv_bfloat16 sm[];
    const int tid = threadIdx.x;
    const int lane = tid & 31;
    const int w = tid >> 5;
    const int rql = lane >> 2;
    const int kof = (lane & 3) << 1;
    const int q0 = blockIdx.x * 64;
    const int z = blockIdx.y;
    const int bb = z >> 3, hh = z & 7;
    const long base = (long)bb * D_ + (long)hh * HD_;
    const int ldr = B_ * D_;

    // ---- Q tile (64 x 96) hi/lo via cp.async
    {
        const int r = tid >> 1;
        const int c0 = (tid & 1) * 48;
        const __nv_bfloat16* sh = Qh_g + (long)(q0 + r) * ldr + base + c0;
        const __nv_bfloat16* sl = Ql_g + (long)(q0 + r) * ldr + base + c0;
        uint32_t dh = smaddr(sm + SQH + r * QP + c0);
        uint32_t dl = smaddr(sm + SQL + r * QP + c0);
#pragma unroll
        for (int j = 0; j < 6; j++) {
            CP16(dh + 16 * j, sh + 8 * j);
            CP16(dl + 16 * j, sl + 8 * j);
        }
        CP_COMMIT();
        CP_WAIT0();
    }
    __syncthreads();

    // ---- Q fragments to registers
    uint32_t Qfh[6][4], Qfl[6][4];
    {
        const int r0 = 16 * w + rql;
#pragma unroll
        for (int kb = 0; kb < 6; kb++) {
            const int kc = kb * 16 + kof;
            Qfh[kb][0] = *(const uint32_t*)(sm + SQH + r0 * QP + kc);
            Qfh[kb][1] = *(const uint32_t*)(sm + SQH + (r0 + 8) * QP + kc);
            Qfh[kb][2] = *(const uint32_t*)(sm + SQH + r0 * QP + kc + 8);
            Qfh[kb][3] = *(const uint32_t*)(sm + SQH + (r0 + 8) * QP + kc + 8);
            Qfl[kb][0] = *(const uint32_t*)(sm + SQL + r0 * QP + kc);
            Qfl[kb][1] = *(const uint32_t*)(sm + SQL + (r0 + 8) * QP + kc);
            Qfl[kb][2] = *(const uint32_t*)(sm + SQL + r0 * QP + kc + 8);
            Qfl[kb][3] = *(const uint32_t*)(sm + SQL + (r0 + 8) * QP + kc + 8);
        }
    }

    float O[12][4];
#pragma unroll
    for (int i = 0; i < 12; i++)
#pragma unroll
        for (int j = 0; j < 4; j++) O[i][j] = 0.f;
    float mrow[2] = {-1e30f, -1e30f};
    float lrow[2] = {0.f, 0.f};

    for (int s0 = 0; s0 < T_; s0 += 64) {
        __syncthreads();
        // ---- K tile hi/lo via cp.async
        {
            const int r = tid >> 1;
            const int c0 = (tid & 1) * 48;
            const __nv_bfloat16* sh = Kh_g + (long)(s0 + r) * ldr + base + c0;
            const __nv_bfloat16* sl = Kl_g + (long)(s0 + r) * ldr + base + c0;
            uint32_t dh = smaddr(sm + SKH + r * QP + c0);
            uint32_t dl = smaddr(sm + SKL + r * QP + c0);
#pragma unroll
            for (int j = 0; j < 6; j++) {
                CP16(dh + 16 * j, sh + 8 * j);
                CP16(dl + 16 * j, sl + 8 * j);
            }
            CP_COMMIT();
        }
        // ---- V tile -> transposed split smem [dim][key] (overlaps K cp.async)
        {
            const int r = (w & 1) * 32 + lane;
            const int c0 = (w >> 1) * 48;
            const __nv_bfloat16* sh = Vh_g + (long)(s0 + r) * ldr + base + c0;
            const __nv_bfloat16* sl = Vl_g + (long)(s0 + r) * ldr + base + c0;
#pragma unroll
            for (int j = 0; j < 6; j++) {
                uint4 vh = *(const uint4*)(sh + 8 * j);
                uint4 vl = *(const uint4*)(sl + 8 * j);
                const ushort* ph = (const ushort*)&vh;
                const ushort* pl = (const ushort*)&vl;
#pragma unroll
                for (int u = 0; u < 8; u++) {
                    sm[SVH + (c0 + 8 * j + u) * VP + r] = __ushort_as_bfloat16(ph[u]);
                    sm[SVL + (c0 + 8 * j + u) * VP + r] = __ushort_as_bfloat16(pl[u]);
                }
            }
        }
        CP_WAIT0();
        __syncthreads();

        // ---- S = Q K^T  (kb outer, nt-block 4, term-major: chain dist 4)
        float S[8][4];
#pragma unroll
        for (int nt = 0; nt < 8; nt++) {
            S[nt][0] = S[nt][1] = S[nt][2] = S[nt][3] = 0.f;
        }
#pragma unroll
        for (int kb = 0; kb < 6; kb++) {
            const int kc = kb * 16 + kof;
#pragma unroll
            for (int nb = 0; nb < 8; nb += 4) {
                uint32_t bh[4][2], bl[4][2];
#pragma unroll
                for (int j = 0; j < 4; j++) {
                    const int n0 = (nb + j) * 8 + rql;
                    bh[j][0] = *(const uint32_t*)(sm + SKH + n0 * QP + kc);
                    bh[j][1] = *(const uint32_t*)(sm + SKH + n0 * QP + kc + 8);
                    bl[j][0] = *(const uint32_t*)(sm + SKL + n0 * QP + kc);
                    bl[j][1] = *(const uint32_t*)(sm + SKL + n0 * QP + kc + 8);
                }
#pragma unroll
                for (int j = 0; j < 4; j++) mma16816(S[nb + j], Qfh[kb], bh[j]);
#pragma unroll
                for (int j = 0; j < 4; j++) mma16816(S[nb + j], Qfl[kb], bh[j]);
#pragma unroll
                for (int j = 0; j < 4; j++) mma16816(S[nb + j], Qfh[kb], bl[j]);
            }
        }

        // ---- base-2 online softmax
        float rmax0 = -1e30f, rmax1 = -1e30f;
#pragma unroll
        for (int nt = 0; nt < 8; nt++) {
            S[nt][0] *= scale2; S[nt][1] *= scale2;
            S[nt][2] *= scale2; S[nt][3] *= scale2;
            rmax0 = fmaxf(rmax0, fmaxf(S[nt][0], S[nt][1]));
            rmax1 = fmaxf(rmax1, fmaxf(S[nt][2], S[nt][3]));
        }
        rmax0 = fmaxf(rmax0, __shfl_xor_sync(0xffffffffu, rmax0, 1));
        rmax0 = fmaxf(rmax0, __shfl_xor_sync(0xffffffffu, rmax0, 2));
        rmax1 = fmaxf(rmax1, __shfl_xor_sync(0xffffffffu, rmax1, 1));
        rmax1 = fmaxf(rmax1, __shfl_xor_sync(0xffffffffu, rmax1, 2));

        const float m0n = fmaxf(mrow[0], rmax0);
        const float m1n = fmaxf(mrow[1], rmax1);
        const float a0 = exp2f(mrow[0] - m0n);
        const float a1 = exp2f(mrow[1] - m1n);
        mrow[0] = m0n; mrow[1] = m1n;

        float rs0 = 0.f, rs1 = 0.f;
#pragma unroll
        for (int nt = 0; nt < 8; nt++) {
            S[nt][0] = exp2f(S[nt][0] - m0n);
            S[nt][1] = exp2f(S[nt][1] - m0n);
            S[nt][2] = exp2f(S[nt][2] - m1n);
            S[nt][3] = exp2f(S[nt][3] - m1n);
            rs0 += S[nt][0] + S[nt][1];
            rs1 += S[nt][2] + S[nt][3];
        }
        rs0 += __shfl_xor_sync(0xffffffffu, rs0, 1);
        rs0 += __shfl_xor_sync(0xffffffffu, rs0, 2);
        rs1 += __shfl_xor_sync(0xffffffffu, rs1, 1);
        rs1 += __shfl_xor_sync(0xffffffffu, rs1, 2);
        lrow[0] = lrow[0] * a0 + rs0;
        lrow[1] = lrow[1] * a1 + rs1;

#pragma unroll
        for (int i = 0; i < 12; i++) {
            O[i][0] *= a0; O[i][1] *= a0;
            O[i][2] *= a1; O[i][3] *= a1;
        }

        // ---- P -> hi/lo A-fragments
        uint32_t Ph[4][4], Pl[4][4];
#pragma unroll
        for (int kb = 0; kb < 4; kb++) {
            const float* s0f = S[2 * kb];
            const float* s1f = S[2 * kb + 1];
            __nv_bfloat16 h00,h01,h02,h03,h10,h11,h12,h13;
            __nv_bfloat16 l00,l01,l02,l03,l10,l11,l12,l13;
            split2(s0f[0],h00,l00); split2(s0f[1],h01,l01);
            split2(s0f[2],h02,l02); split2(s0f[3],h03,l03);
            split2(s1f[0],h10,l10); split2(s1f[1],h11,l11);
            split2(s1f[2],h12,l12); split2(s1f[3],h13,l13);
            Ph[kb][0] = pack2(h00, h01); Ph[kb][1] = pack2(h02, h03);
            Ph[kb][2] = pack2(h10, h11); Ph[kb][3] = pack2(h12, h13);
            Pl[kb][0] = pack2(l00, l01); Pl[kb][1] = pack2(l02, l03);
            Pl[kb][2] = pack2(l10, l11); Pl[kb][3] = pack2(l12, l13);
        }

        // ---- O += P @ V^T  (kb outer, nt-block 4, term-major: chain dist 4)
#pragma unroll
        for (int kb = 0; kb < 4; kb++) {
            const int kc = kb * 16 + kof;
#pragma unroll
            for (int nb = 0; nb < 12; nb += 4) {
                uint32_t bh[4][2], bl[4][2];
#pragma unroll
                for (int j = 0; j < 4; j++) {
                    const int n0 = (nb + j) * 8 + rql;
                    bh[j][0] = *(const uint32_t*)(sm + SVH + n0 * VP + kc);
                    bh[j][1] = *(const uint32_t*)(sm + SVH + n0 * VP + kc + 8);
                    bl[j][0] = *(const uint32_t*)(sm + SVL + n0 * VP + kc);
                    bl[j][1] = *(const uint32_t*)(sm + SVL + n0 * VP + kc + 8);
                }
#pragma unroll
                for (int j = 0; j < 4; j++) mma16816(O[nb + j], Ph[kb], bh[j]);
#pragma unroll
                for (int j = 0; j < 4; j++) mma16816(O[nb + j], Pl[kb], bh[j]);
#pragma unroll
                for (int j = 0; j < 4; j++) mma16816(O[nb + j], Ph[kb], bl[j]);
            }
        }
    }

    // ---- epilogue: normalize, split, write hi/lo
    const float inv0 = 1.f / lrow[0];
    const float inv1 = 1.f / lrow[1];
    const int r0 = q0 + 16 * w + rql;
#pragma unroll
    for (int nt = 0; nt < 12; nt++) {
        const int cb = nt * 8 + kof;
        const long o0 = (long)r0 * ldr + base + cb;
        const long o1 = (long)(r0 + 8) * ldr + base + cb;
        __nv_bfloat16 h0,h1,h2,h3,l0,l1,l2,l3;
        split2(O[nt][0] * inv0, h0, l0);
        split2(O[nt][1] * inv0, h1, l1);
        split2(O[nt][2] * inv1, h2, l2);
        split2(O[nt][3] * inv1, h3, l3);
        *(uint32_t*)(Oh_g + o0) = pack2(h0, h1);
        *(uint32_t*)(Ol_g + o0) = pack2(l0, l1);
        *(uint32_t*)(Oh_g + o1) = pack2(h2, h3);
        *(uint32_t*)(Ol_g + o1) = pack2(l2, l3);
    }
}

// ================= HMMA GEMM, pre-split bf16 inputs, cp.async (R10, KC=32) =================
#define KC 32
#define PA 40
#define TILE_E (128 * PA)
#define GEMM_SMEM (2 * 4 * TILE_E * 2)

__device__ __forceinline__
void gemm_body(__nv_bfloat16* sm,
               const __nv_bfloat16* __restrict__ Ah, const __nv_bfloat16* __restrict__ Al,
               const __nv_bfloat16* __restrict__ Bh, const __nv_bfloat16* __restrict__ Bl,
               const float* __restrict__ bias, const float* __restrict__ residual,
               float* __restrict__ Cf,
               __nv_bfloat16* __restrict__ Ch, __nv_bfloat16* __restrict__ Cl,
               int K, int lda, int ldb, int ldc, int relu)
{
    const int tid = threadIdx.x;
    const int lane = tid & 31;
    const int wid = tid >> 5;
    const int warpM = wid >> 2;
    const int warpN = wid & 3;
    const int rowBase = blockIdx.y * 128;
    const int colBase = blockIdx.x * 128;

    const int r = tid >> 1;            // 0..127
    const int hf = (tid & 1) << 4;     // 0 or 16 elems

    auto issue = [&](int k0, int buf) {
        __nv_bfloat16* pAh = sm + buf * 4 * TILE_E;
        const long aoff = (long)(rowBase + r) * lda + k0 + hf;
        const long boff = (long)(colBase + r) * ldb + k0 + hf;
        const uint32_t d = smaddr(&pAh[r * PA + hf]);
        CP16(d,                        Ah + aoff);
        CP16(d + 16,                   Ah + aoff + 8);
        CP16(d + TILE_E * 2,           Al + aoff);
        CP16(d + TILE_E * 2 + 16,      Al + aoff + 8);
        CP16(d + TILE_E * 4,           Bh + boff);
        CP16(d + TILE_E * 4 + 16,      Bh + boff + 8);
        CP16(d + TILE_E * 6,           Bl + boff);
        CP16(d + TILE_E * 6 + 16,      Bl + boff + 8);
        CP_COMMIT();
    };

    float acc[4][4][4];
#pragma unroll
    for (int i = 0; i < 4; i++)
#pragma unroll
        for (int j = 0; j < 4; j++)
#pragma unroll
            for (int rr = 0; rr < 4; rr++) acc[i][j][rr] = 0.f;

    const int NC = K / KC;
    issue(0, 0);
    CP_WAIT0();
    __syncthreads();

    int buf = 0;
    for (int c = 0; c < NC; c++) {
        const bool has = (c + 1) < NC;
        if (has) issue((c + 1) * KC, buf ^ 1);

        const __nv_bfloat16* pAh = sm + buf * 4 * TILE_E;
        const __nv_bfloat16* pAl = pAh + TILE_E;
        const __nv_bfloat16* pBh = pAh + 2 * TILE_E;
        const __nv_bfloat16* pBl = pAh + 3 * TILE_E;
        const int rql = lane >> 2;
        const int kof = (lane & 3) << 1;

#pragma unroll
        for (int ks = 0; ks < KC; ks += 16) {
            const int kcol = ks + kof;
            uint32_t bh[4][2], bl[4][2];
#pragma unroll
            for (int nt = 0; nt < 4; nt++) {
                const int n0 = warpN * 32 + nt * 8 + rql;
                bh[nt][0] = *(const uint32_t*)&pBh[n0 * PA + kcol];
                bh[nt][1] = *(const uint32_t*)&pBh[n0 * PA + kcol + 8];
                bl[nt][0] = *(const uint32_t*)&pBl[n0 * PA + kcol];
                bl[nt][1] = *(const uint32_t*)&pBl[n0 * PA + kcol + 8];
            }
            uint32_t ah[4][4], al[4][4];
#pragma unroll
            for (int mt = 0; mt < 4; mt++) {
                const int r0 = warpM * 64 + mt * 16 + rql;
                ah[mt][0] = *(const uint32_t*)&pAh[r0 * PA + kcol];
                ah[mt][1] = *(const uint32_t*)&pAh[(r0 + 8) * PA + kcol];
                ah[mt][2] = *(const uint32_t*)&pAh[r0 * PA + kcol + 8];
                ah[mt][3] = *(const uint32_t*)&pAh[(r0 + 8) * PA + kcol + 8];
                al[mt][0] = *(const uint32_t*)&pAl[r0 * PA + kcol];
                al[mt][1] = *(const uint32_t*)&pAl[(r0 + 8) * PA + kcol];
                al[mt][2] = *(const uint32_t*)&pAl[r0 * PA + kcol + 8];
                al[mt][3] = *(const uint32_t*)&pAl[(r0 + 8) * PA + kcol + 8];
            }
            // term-major: 16 independent MMAs between accumulator reuses
#pragma unroll
            for (int mt = 0; mt < 4; mt++)
#pragma unroll
                for (int nt = 0; nt < 4; nt++)
                    mma16816(acc[mt][nt], ah[mt], bh[nt]);
#pragma unroll
            for (int mt = 0; mt < 4; mt++)
#pragma unroll
                for (int nt = 0; nt < 4; nt++)
                    mma16816(acc[mt][nt], al[mt], bh[nt]);
#pragma unroll
            for (int mt = 0; mt < 4; mt++)
#pragma unroll
                for (int nt = 0; nt < 4; nt++)
                    mma16816(acc[mt][nt], ah[mt], bl[nt]);
        }

        if (has) CP_WAIT0();
        __syncthreads();
        buf ^= 1;
    }

    const int rql = lane >> 2;
    const int cof = (lane & 3) << 1;
#pragma unroll
    for (int mt = 0; mt < 4; mt++) {
        const int r0 = rowBase + warpM * 64 + mt * 16 + rql;
#pragma unroll
        for (int nt = 0; nt < 4; nt++) {
            const int cb = colBase + warpN * 32 + nt * 8 + cof;
            float* a4 = acc[mt][nt];
            float2 bb = make_float2(0.f, 0.f);
            if (bias) bb = *(const float2*)(bias + cb);
            float v0 = a4[0] + bb.x;
            float v1 = a4[1] + bb.y;
            float v2 = a4[2] + bb.x;
            float v3 = a4[3] + bb.y;
            if (relu) {
                v0 = fmaxf(v0, 0.f); v1 = fmaxf(v1, 0.f);
                v2 = fmaxf(v2, 0.f); v3 = fmaxf(v3, 0.f);
            }
            const long o0 = (long)r0 * ldc + cb;
            const long o1 = (long)(r0 + 8) * ldc + cb;
            if (residual) {
                float2 r00 = *(const float2*)(residual + o0);
                float2 r11 = *(const float2*)(residual + o1);
                v0 += r00.x; v1 += r00.y; v2 += r11.x; v3 += r11.y;
            }
            if (Cf) {
                *(float2*)(Cf + o0) = make_float2(v0, v1);
                *(float2*)(Cf + o1) = make_float2(v2, v3);
            }
            if (Ch) {
                __nv_bfloat16 h0,h1,h2,h3,l0,l1,l2,l3;
                split2(v0, h0, l0); split2(v1, h1, l1);
                split2(v2, h2, l2); split2(v3, h3, l3);
                *(uint32_t*)(Ch + o0) = pack2(h0, h1);
                *(uint32_t*)(Cl + o0) = pack2(l0, l1);
                *(uint32_t*)(Ch + o1) = pack2(h2, h3);
                *(uint32_t*)(Cl + o1) = pack2(l2, l3);
            }
        }
    }
}

__global__ __launch_bounds__(256, 2)
void gemm_hmma(const __nv_bfloat16* Ah, const __nv_bfloat16* Al,
               const __nv_bfloat16* Bh, const __nv_bfloat16* Bl,
               const float* bias, const float* residual,
               float* Cf, __nv_bfloat16* Ch, __nv_bfloat16* Cl,
               int K, int lda, int ldb, int ldc, int relu)
{
    extern __shared__ char dsm[];
    gemm_body((__nv_bfloat16*)dsm, Ah, Al, Bh, Bl, bias, residual,
              Cf, Ch, Cl, K, lda, ldb, ldc, relu);
}

// fused QKV: blockIdx.z selects weight/bias/output; emits split outputs
__global__ __launch_bounds__(256, 2)
void gemm_qkv(const __nv_bfloat16* xh, const __nv_bfloat16* xl,
              const __nv_bfloat16* w0h, const __nv_bfloat16* w0l,
              const __nv_bfloat16* w1h, const __nv_bfloat16* w1l,
              const __nv_bfloat16* w2h, const __nv_bfloat16* w2l,
              const float* b0, const float* b1, const float* b2,
              __nv_bfloat16* c0h, __nv_bfloat16* c0l,
              __nv_bfloat16* c1h, __nv_bfloat16* c1l,
              __nv_bfloat16* c2h, __nv_bfloat16* c2l)
{
    extern __shared__ char dsm[];
    const int z = blockIdx.z;
    const __nv_bfloat16* Bh = (z == 0) ? w0h : (z == 1) ? w1h : w2h;
    const __nv_bfloat16* Bl = (z == 0) ? w0l : (z == 1) ? w1l : w2l;
    const float* bias = (z == 0) ? b0 : (z == 1) ? b1 : b2;
    __nv_bfloat16* Ch = (z == 0) ? c0h : (z == 1) ? c1h : c2h;
    __nv_bfloat16* Cl = (z == 0) ? c0l : (z == 1) ? c1l : c2l;
    gemm_body((__nv_bfloat16*)dsm, xh, xl, Bh, Bl, bias, nullptr,
              nullptr, Ch, Cl, D_, D_, D_, D_, 0);
}

// ---------------- block reduction ----------------
__device__ __forceinline__ float blockReduceSum(float v) {
    __shared__ float s[8];
#pragma unroll
    for (int o = 16; o > 0; o >>= 1) v += __shfl_xor_sync(0xffffffffu, v, o);
    int w = threadIdx.x >> 5, l = threadIdx.x & 31;
    if (l == 0) s[w] = v;
    __syncthreads();
    if (threadIdx.x < 32) {
        v = (threadIdx.x < 8) ? s[threadIdx.x] : 0.f;
#pragma unroll
        for (int o = 4; o > 0; o >>= 1) v += __shfl_xor_sync(0xffffffffu, v, o);
        if (threadIdx.x == 0) s[0] = v;
    }
    __syncthreads();
    v = s[0];
    __syncthreads();
    return v;
}

// ---------------- layernorm (optional split emit) ----------------
__global__ void layernorm_kernel(const float* __restrict__ X,
                                 const float* __restrict__ g,
                                 const float* __restrict__ b,
                                 float* __restrict__ Y,
                                 __nv_bfloat16* __restrict__ Yh,
                                 __nv_bfloat16* __restrict__ Yl) {
    long row = blockIdx.x;
    const float* p = X + row * D_;
    int tid = threadIdx.x;
    float vals[3];
    float sum = 0.f;
#pragma unroll
    for (int i = 0; i < 3; i++) {
        vals[i] = p[tid + i * 256];
        sum += vals[i];
    }
    float mu = blockReduceSum(sum) * (1.f / D_);
    float vs = 0.f;
#pragma unroll
    for (int i = 0; i < 3; i++) {
        float d = vals[i] - mu;
        vs += d * d;
    }
    float var = blockReduceSum(vs) * (1.f / D_);
    float rs = rsqrtf(var + 1e-5f);
#pragma unroll
    for (int i = 0; i < 3; i++) {
        int c = tid + i * 256;
        float o = (vals[i] - mu) * rs * g[c] + b[c];
        if (Y) Y[row * D_ + c] = o;
        if (Yh) {
            __nv_bfloat16 h, l;
            split2(o, h, l);
            Yh[row * D_ + c] = h;
            Yl[row * D_ + c] = l;
        }
    }
}

// ---------------- launch ----------------
extern "C" void kernel_launch(void* const* d_in, const int* in_sizes, int n_in,
                              void* d_out, int out_size)
{
    const float* x     = (const float*)d_in[0];
    const float* wq    = (const float*)d_in[1];
    const float* bq    = (const float*)d_in[2];
    const float* wk    = (const float*)d_in[3];
    const float* bk    = (const float*)d_in[4];
    const float* wv    = (const float*)d_in[5];
    const float* bv    = (const float*)d_in[6];
    const float* wo    = (const float*)d_in[7];
    const float* bo    = (const float*)d_in[8];
    const float* ln1g  = (const float*)d_in[9];
    const float* ln1b  = (const float*)d_in[10];
    const float* w1    = (const float*)d_in[11];
    const float* b1    = (const float*)d_in[12];
    const float* w2    = (const float*)d_in[13];
    const float* b2    = (const float*)d_in[14];
    const float* ln2g  = (const float*)d_in[15];
    const float* ln2b  = (const float*)d_in[16];
    float* out = (float*)d_out;

    float *tmp1, *x1, *y;
    cudaGetSymbolAddress((void**)&tmp1, g_tmp1);
    cudaGetSymbolAddress((void**)&x1,   g_x1);
    cudaGetSymbolAddress((void**)&y,    g_y);

    __nv_bfloat16 *xh,*xl,*qh,*ql,*kh,*kl,*vh,*vl,*ah,*al,*x1h,*x1l,*h1h,*h1l;
    __nv_bfloat16 *wqh,*wql,*wkh,*wkl,*wvh,*wvl,*woh,*wol,*w1h,*w1l,*w2h,*w2l;
    cudaGetSymbolAddress((void**)&xh, g_xh);   cudaGetSymbolAddress((void**)&xl, g_xl);
    cudaGetSymbolAddress((void**)&qh, g_qh);   cudaGetSymbolAddress((void**)&ql, g_ql);
    cudaGetSymbolAddress((void**)&kh, g_kh);   cudaGetSymbolAddress((void**)&kl, g_kl);
    cudaGetSymbolAddress((void**)&vh, g_vh);   cudaGetSymbolAddress((void**)&vl, g_vl);
    cudaGetSymbolAddress((void**)&ah, g_ah);   cudaGetSymbolAddress((void**)&al, g_al);
    cudaGetSymbolAddress((void**)&x1h, g_x1h); cudaGetSymbolAddress((void**)&x1l, g_x1l);
    cudaGetSymbolAddress((void**)&h1h, g_h1h); cudaGetSymbolAddress((void**)&h1l, g_h1l);
    cudaGetSymbolAddress((void**)&wqh, g_wqh); cudaGetSymbolAddress((void**)&wql, g_wql);
    cudaGetSymbolAddress((void**)&wkh, g_wkh); cudaGetSymbolAddress((void**)&wkl, g_wkl);
    cudaGetSymbolAddress((void**)&wvh, g_wvh); cudaGetSymbolAddress((void**)&wvl, g_wvl);
    cudaGetSymbolAddress((void**)&woh, g_woh); cudaGetSymbolAddress((void**)&wol, g_wol);
    cudaGetSymbolAddress((void**)&w1h, g_w1h); cudaGetSymbolAddress((void**)&w1l, g_w1l);
    cudaGetSymbolAddress((void**)&w2h, g_w2h); cudaGetSymbolAddress((void**)&w2l, g_w2l);

    cudaFuncSetAttribute(gemm_hmma, cudaFuncAttributeMaxDynamicSharedMemorySize, GEMM_SMEM);
    cudaFuncSetAttribute(gemm_qkv,  cudaFuncAttributeMaxDynamicSharedMemorySize, GEMM_SMEM);
    cudaFuncSetAttribute(flash_attn, cudaFuncAttributeMaxDynamicSharedMemorySize, FLASH_SMEM);

    const float scale2 = 0.102062072615966f * 1.44269504088896f;
    dim3 blk(256);

    // ---- one-time splits (x + all weights, single launch)
    split_all<<<SPLIT_BLOCKS, blk>>>(x, wq, wk, wv, wo, w1, w2,
                                     xh, xl, wqh, wql, wkh, wkl, wvh, wvl,
                                     woh, wol, w1h, w1l, w2h, w2l);

    // ---- QKV projections (fused; split outputs feed flash)
    dim3 gQKV(D_ / 128, NR_ / 128, 3);
    gemm_qkv<<<gQKV, blk, GEMM_SMEM>>>(xh, xl, wqh, wql, wkh, wkl, wvh, wvl,
                                       bq, bk, bv, qh, ql, kh, kl, vh, vl);

    // ---- flash attention (split in, split out)
    dim3 gFA(T_ / 64, BH_);
    flash_attn<<<gFA, dim3(128), FLASH_SMEM>>>(qh, ql, kh, kl, vh, vl, ah, al, scale2);

    // ---- O projection + residual(x) -> tmp1 (fp32)
    dim3 gProj(D_ / 128, NR_ / 128);
    gemm_hmma<<<gProj, blk, GEMM_SMEM>>>(ah, al, woh, wol, bo, x,
                                         tmp1, nullptr, nullptr, D_, D_, D_, D_, 0);

    // ---- LN1 -> x1 fp32 + split
    layernorm_kernel<<<NR_, blk>>>(tmp1, ln1g, ln1b, x1, x1h, x1l);

    // ---- FFN1: relu -> h1 split only
    dim3 gF1(FFN_ / 128, NR_ / 128);
    gemm_hmma<<<gF1, blk, GEMM_SMEM>>>(x1h, x1l, w1h, w1l, b1, nullptr,
                                       nullptr, h1h, h1l, D_, D_, D_, FFN_, 1);

    // ---- FFN2 + residual(x1) -> y fp32
    gemm_hmma<<<gProj, blk, GEMM_SMEM>>>(h1h, h1l, w2h, w2l, b2, x1,
                                         y, nullptr, nullptr, FFN_, FFN_, FFN_, D_, 0);

    // ---- LN2 -> out
    layernorm_kernel<<<NR_, blk>>>(y, ln2g, ln2b, out, nullptr, nullptr);
}

// round 17
// speedup vs baseline: 1.1336x; 1.0308x over previous
#include <cuda_runtime.h>
#include <cuda_bf16.h>
#include <math.h>
#include <stdint.h>

// Problem constants
#define T_ 2048
#define B_ 2
#define D_ 768
#define H_ 8
#define HD_ 96
#define FFN_ 3072
#define NR_ (T_ * B_)          // 4096 rows
#define BH_ (B_ * H_)          // 16 attention batches

// ---------------- scratch ----------------
__device__ float g_tmp1[NR_ * D_];
__device__ float g_x1[NR_ * D_];
__device__ float g_y[NR_ * D_];

// bf16 hi/lo split buffers
__device__ __nv_bfloat16 g_xh[NR_ * D_],  g_xl[NR_ * D_];
__device__ __nv_bfloat16 g_qh[NR_ * D_],  g_ql[NR_ * D_];
__device__ __nv_bfloat16 g_kh[NR_ * D_],  g_kl[NR_ * D_];
__device__ __nv_bfloat16 g_vh[NR_ * D_],  g_vl[NR_ * D_];
__device__ __nv_bfloat16 g_ah[NR_ * D_],  g_al[NR_ * D_];
__device__ __nv_bfloat16 g_x1h[NR_ * D_], g_x1l[NR_ * D_];
__device__ __nv_bfloat16 g_h1h[NR_ * FFN_], g_h1l[NR_ * FFN_];
__device__ __nv_bfloat16 g_wqh[D_ * D_], g_wql[D_ * D_];
__device__ __nv_bfloat16 g_wkh[D_ * D_], g_wkl[D_ * D_];
__device__ __nv_bfloat16 g_wvh[D_ * D_], g_wvl[D_ * D_];
__device__ __nv_bfloat16 g_woh[D_ * D_], g_wol[D_ * D_];
__device__ __nv_bfloat16 g_w1h[FFN_ * D_], g_w1l[FFN_ * D_];
__device__ __nv_bfloat16 g_w2h[D_ * FFN_], g_w2l[D_ * FFN_];

// ================= helpers =================
__device__ __forceinline__ uint32_t pack2(__nv_bfloat16 a, __nv_bfloat16 b) {
    return (uint32_t)__bfloat16_as_ushort(a) | ((uint32_t)__bfloat16_as_ushort(b) << 16);
}
__device__ __forceinline__ void split2(float v, __nv_bfloat16& h, __nv_bfloat16& l) {
    h = __float2bfloat16(v);
    l = __float2bfloat16(v - __bfloat162float(h));
}
__device__ __forceinline__ void mma16816(float* c, const uint32_t* a, const uint32_t* b) {
    asm volatile(
        "mma.sync.aligned.m16n8k16.row.col.f32.bf16.bf16.f32 "
        "{%0,%1,%2,%3}, {%4,%5,%6,%7}, {%8,%9}, {%0,%1,%2,%3};"
        : "+f"(c[0]), "+f"(c[1]), "+f"(c[2]), "+f"(c[3])
        : "r"(a[0]), "r"(a[1]), "r"(a[2]), "r"(a[3]), "r"(b[0]), "r"(b[1]));
}
__device__ __forceinline__ uint32_t smaddr(const void* p) {
    return (uint32_t)__cvta_generic_to_shared(p);
}
#define CP16(dst, src) \
    asm volatile("cp.async.cg.shared.global [%0], [%1], 16;" :: "r"(dst), "l"(src))
#define CP_COMMIT() asm volatile("cp.async.commit_group;" ::: "memory")
#define CP_WAIT0()  asm volatile("cp.async.wait_group 0;" ::: "memory")

// ================= fused split kernel (7 regions, 1 launch) =================
#define SPLIT_BLOCKS 9984
__global__ void split_all(const float* __restrict__ x,
                          const float* __restrict__ wq, const float* __restrict__ wk,
                          const float* __restrict__ wv, const float* __restrict__ wo,
                          const float* __restrict__ w1, const float* __restrict__ w2,
                          __nv_bfloat16* xh, __nv_bfloat16* xl,
                          __nv_bfloat16* wqh, __nv_bfloat16* wql,
                          __nv_bfloat16* wkh, __nv_bfloat16* wkl,
                          __nv_bfloat16* wvh, __nv_bfloat16* wvl,
                          __nv_bfloat16* woh, __nv_bfloat16* wol,
                          __nv_bfloat16* w1h, __nv_bfloat16* w1l,
                          __nv_bfloat16* w2h, __nv_bfloat16* w2l)
{
    int bid = blockIdx.x;
    const float* in; __nv_bfloat16 *hi, *lo; int start;
    if      (bid < 3072) { in = x;  hi = xh;  lo = xl;  start = 0; }
    else if (bid < 3648) { in = wq; hi = wqh; lo = wql; start = 3072; }
    else if (bid < 4224) { in = wk; hi = wkh; lo = wkl; start = 3648; }
    else if (bid < 4800) { in = wv; hi = wvh; lo = wvl; start = 4224; }
    else if (bid < 5376) { in = wo; hi = woh; lo = wol; start = 4800; }
    else if (bid < 7680) { in = w1; hi = w1h; lo = w1l; start = 5376; }
    else                 { in = w2; hi = w2h; lo = w2l; start = 7680; }
    int i = (bid - start) * 1024 + threadIdx.x * 4;
    float4 v = *(const float4*)(in + i);
    __nv_bfloat16 h0, h1, h2, h3, l0, l1, l2, l3;
    split2(v.x, h0, l0); split2(v.y, h1, l1);
    split2(v.z, h2, l2); split2(v.w, h3, l3);
    *(uint2*)(hi + i) = make_uint2(pack2(h0, h1), pack2(h2, h3));
    *(uint2*)(lo + i) = make_uint2(pack2(l0, l1), pack2(l2, l3));
}

// ================= flash attention (R10 version — best measured) =================
#define QP 104
#define VP 72
#define SQH 0
#define SQL 6656
#define SKH 13312
#define SKL 19968
#define SVH 26624
#define SVL 33536
#define FLASH_SMEM (40448 * 2)

__global__ __launch_bounds__(128, 2)
void flash_attn(const __nv_bfloat16* __restrict__ Qh_g, const __nv_bfloat16* __restrict__ Ql_g,
                const __nv_bfloat16* __restrict__ Kh_g, const __nv_bfloat16* __restrict__ Kl_g,
                const __nv_bfloat16* __restrict__ Vh_g, const __nv_bfloat16* __restrict__ Vl_g,
                __nv_bfloat16* __restrict__ Oh_g, __nv_bfloat16* __restrict__ Ol_g,
                float scale2)
{
    extern __shared__ __nv_bfloat16 sm[];
    const int tid = threadIdx.x;
    const int lane = tid & 31;
    const int w = tid >> 5;
    const int rql = lane >> 2;
    const int kof = (lane & 3) << 1;
    const int q0 = blockIdx.x * 64;
    const int z = blockIdx.y;
    const int bb = z >> 3, hh = z & 7;
    const long base = (long)bb * D_ + (long)hh * HD_;
    const int ldr = B_ * D_;

    // ---- Q tile (64 x 96) hi/lo via cp.async
    {
        const int r = tid >> 1;
        const int c0 = (tid & 1) * 48;
        const __nv_bfloat16* sh = Qh_g + (long)(q0 + r) * ldr + base + c0;
        const __nv_bfloat16* sl = Ql_g + (long)(q0 + r) * ldr + base + c0;
        uint32_t dh = smaddr(sm + SQH + r * QP + c0);
        uint32_t dl = smaddr(sm + SQL + r * QP + c0);
#pragma unroll
        for (int j = 0; j < 6; j++) {
            CP16(dh + 16 * j, sh + 8 * j);
            CP16(dl + 16 * j, sl + 8 * j);
        }
        CP_COMMIT();
        CP_WAIT0();
    }
    __syncthreads();

    // ---- Q fragments to registers
    uint32_t Qfh[6][4], Qfl[6][4];
    {
        const int r0 = 16 * w + rql;
#pragma unroll
        for (int kb = 0; kb < 6; kb++) {
            const int kc = kb * 16 + kof;
            Qfh[kb][0] = *(const uint32_t*)(sm + SQH + r0 * QP + kc);
            Qfh[kb][1] = *(const uint32_t*)(sm + SQH + (r0 + 8) * QP + kc);
            Qfh[kb][2] = *(const uint32_t*)(sm + SQH + r0 * QP + kc + 8);
            Qfh[kb][3] = *(const uint32_t*)(sm + SQH + (r0 + 8) * QP + kc + 8);
            Qfl[kb][0] = *(const uint32_t*)(sm + SQL + r0 * QP + kc);
            Qfl[kb][1] = *(const uint32_t*)(sm + SQL + (r0 + 8) * QP + kc);
            Qfl[kb][2] = *(const uint32_t*)(sm + SQL + r0 * QP + kc + 8);
            Qfl[kb][3] = *(const uint32_t*)(sm + SQL + (r0 + 8) * QP + kc + 8);
        }
    }

    float O[12][4];
#pragma unroll
    for (int i = 0; i < 12; i++)
#pragma unroll
        for (int j = 0; j < 4; j++) O[i][j] = 0.f;
    float mrow[2] = {-1e30f, -1e30f};
    float lrow[2] = {0.f, 0.f};

    for (int s0 = 0; s0 < T_; s0 += 64) {
        __syncthreads();
        // ---- K tile hi/lo via cp.async
        {
            const int r = tid >> 1;
            const int c0 = (tid & 1) * 48;
            const __nv_bfloat16* sh = Kh_g + (long)(s0 + r) * ldr + base + c0;
            const __nv_bfloat16* sl = Kl_g + (long)(s0 + r) * ldr + base + c0;
            uint32_t dh = smaddr(sm + SKH + r * QP + c0);
            uint32_t dl = smaddr(sm + SKL + r * QP + c0);
#pragma unroll
            for (int j = 0; j < 6; j++) {
                CP16(dh + 16 * j, sh + 8 * j);
                CP16(dl + 16 * j, sl + 8 * j);
            }
            CP_COMMIT();
        }
        // ---- V tile -> transposed split smem [dim][key] (overlaps K cp.async)
        {
            const int r = (w & 1) * 32 + lane;
            const int c0 = (w >> 1) * 48;
            const __nv_bfloat16* sh = Vh_g + (long)(s0 + r) * ldr + base + c0;
            const __nv_bfloat16* sl = Vl_g + (long)(s0 + r) * ldr + base + c0;
#pragma unroll
            for (int j = 0; j < 6; j++) {
                uint4 vh = *(const uint4*)(sh + 8 * j);
                uint4 vl = *(const uint4*)(sl + 8 * j);
                const ushort* ph = (const ushort*)&vh;
                const ushort* pl = (const ushort*)&vl;
#pragma unroll
                for (int u = 0; u < 8; u++) {
                    sm[SVH + (c0 + 8 * j + u) * VP + r] = __ushort_as_bfloat16(ph[u]);
                    sm[SVL + (c0 + 8 * j + u) * VP + r] = __ushort_as_bfloat16(pl[u]);
                }
            }
        }
        CP_WAIT0();
        __syncthreads();

        // ---- S = Q K^T  (kb outer, nt-block 4, term-major: chain dist 4)
        float S[8][4];
#pragma unroll
        for (int nt = 0; nt < 8; nt++) {
            S[nt][0] = S[nt][1] = S[nt][2] = S[nt][3] = 0.f;
        }
#pragma unroll
        for (int kb = 0; kb < 6; kb++) {
            const int kc = kb * 16 + kof;
#pragma unroll
            for (int nb = 0; nb < 8; nb += 4) {
                uint32_t bh[4][2], bl[4][2];
#pragma unroll
                for (int j = 0; j < 4; j++) {
                    const int n0 = (nb + j) * 8 + rql;
                    bh[j][0] = *(const uint32_t*)(sm + SKH + n0 * QP + kc);
                    bh[j][1] = *(const uint32_t*)(sm + SKH + n0 * QP + kc + 8);
                    bl[j][0] = *(const uint32_t*)(sm + SKL + n0 * QP + kc);
                    bl[j][1] = *(const uint32_t*)(sm + SKL + n0 * QP + kc + 8);
                }
#pragma unroll
                for (int j = 0; j < 4; j++) mma16816(S[nb + j], Qfh[kb], bh[j]);
#pragma unroll
                for (int j = 0; j < 4; j++) mma16816(S[nb + j], Qfl[kb], bh[j]);
#pragma unroll
                for (int j = 0; j < 4; j++) mma16816(S[nb + j], Qfh[kb], bl[j]);
            }
        }

        // ---- base-2 online softmax
        float rmax0 = -1e30f, rmax1 = -1e30f;
#pragma unroll
        for (int nt = 0; nt < 8; nt++) {
            S[nt][0] *= scale2; S[nt][1] *= scale2;
            S[nt][2] *= scale2; S[nt][3] *= scale2;
            rmax0 = fmaxf(rmax0, fmaxf(S[nt][0], S[nt][1]));
            rmax1 = fmaxf(rmax1, fmaxf(S[nt][2], S[nt][3]));
        }
        rmax0 = fmaxf(rmax0, __shfl_xor_sync(0xffffffffu, rmax0, 1));
        rmax0 = fmaxf(rmax0, __shfl_xor_sync(0xffffffffu, rmax0, 2));
        rmax1 = fmaxf(rmax1, __shfl_xor_sync(0xffffffffu, rmax1, 1));
        rmax1 = fmaxf(rmax1, __shfl_xor_sync(0xffffffffu, rmax1, 2));

        const float m0n = fmaxf(mrow[0], rmax0);
        const float m1n = fmaxf(mrow[1], rmax1);
        const float a0 = exp2f(mrow[0] - m0n);
        const float a1 = exp2f(mrow[1] - m1n);
        mrow[0] = m0n; mrow[1] = m1n;

        float rs0 = 0.f, rs1 = 0.f;
#pragma unroll
        for (int nt = 0; nt < 8; nt++) {
            S[nt][0] = exp2f(S[nt][0] - m0n);
            S[nt][1] = exp2f(S[nt][1] - m0n);
            S[nt][2] = exp2f(S[nt][2] - m1n);
            S[nt][3] = exp2f(S[nt][3] - m1n);
            rs0 += S[nt][0] + S[nt][1];
            rs1 += S[nt][2] + S[nt][3];
        }
        rs0 += __shfl_xor_sync(0xffffffffu, rs0, 1);
        rs0 += __shfl_xor_sync(0xffffffffu, rs0, 2);
        rs1 += __shfl_xor_sync(0xffffffffu, rs1, 1);
        rs1 += __shfl_xor_sync(0xffffffffu, rs1, 2);
        lrow[0] = lrow[0] * a0 + rs0;
        lrow[1] = lrow[1] * a1 + rs1;

#pragma unroll
        for (int i = 0; i < 12; i++) {
            O[i][0] *= a0; O[i][1] *= a0;
            O[i][2] *= a1; O[i][3] *= a1;
        }

        // ---- P -> hi/lo A-fragments
        uint32_t Ph[4][4], Pl[4][4];
#pragma unroll
        for (int kb = 0; kb < 4; kb++) {
            const float* s0f = S[2 * kb];
            const float* s1f = S[2 * kb + 1];
            __nv_bfloat16 h00,h01,h02,h03,h10,h11,h12,h13;
            __nv_bfloat16 l00,l01,l02,l03,l10,l11,l12,l13;
            split2(s0f[0],h00,l00); split2(s0f[1],h01,l01);
            split2(s0f[2],h02,l02); split2(s0f[3],h03,l03);
            split2(s1f[0],h10,l10); split2(s1f[1],h11,l11);
            split2(s1f[2],h12,l12); split2(s1f[3],h13,l13);
            Ph[kb][0] = pack2(h00, h01); Ph[kb][1] = pack2(h02, h03);
            Ph[kb][2] = pack2(h10, h11); Ph[kb][3] = pack2(h12, h13);
            Pl[kb][0] = pack2(l00, l01); Pl[kb][1] = pack2(l02, l03);
            Pl[kb][2] = pack2(l10, l11); Pl[kb][3] = pack2(l12, l13);
        }

        // ---- O += P @ V^T  (kb outer, nt-block 4, term-major: chain dist 4)
#pragma unroll
        for (int kb = 0; kb < 4; kb++) {
            const int kc = kb * 16 + kof;
#pragma unroll
            for (int nb = 0; nb < 12; nb += 4) {
                uint32_t bh[4][2], bl[4][2];
#pragma unroll
                for (int j = 0; j < 4; j++) {
                    const int n0 = (nb + j) * 8 + rql;
                    bh[j][0] = *(const uint32_t*)(sm + SVH + n0 * VP + kc);
                    bh[j][1] = *(const uint32_t*)(sm + SVH + n0 * VP + kc + 8);
                    bl[j][0] = *(const uint32_t*)(sm + SVL + n0 * VP + kc);
                    bl[j][1] = *(const uint32_t*)(sm + SVL + n0 * VP + kc + 8);
                }
#pragma unroll
                for (int j = 0; j < 4; j++) mma16816(O[nb + j], Ph[kb], bh[j]);
#pragma unroll
                for (int j = 0; j < 4; j++) mma16816(O[nb + j], Pl[kb], bh[j]);
#pragma unroll
                for (int j = 0; j < 4; j++) mma16816(O[nb + j], Ph[kb], bl[j]);
            }
        }
    }

    // ---- epilogue: normalize, split, write hi/lo
    const float inv0 = 1.f / lrow[0];
    const float inv1 = 1.f / lrow[1];
    const int r0 = q0 + 16 * w + rql;
#pragma unroll
    for (int nt = 0; nt < 12; nt++) {
        const int cb = nt * 8 + kof;
        const long o0 = (long)r0 * ldr + base + cb;
        const long o1 = (long)(r0 + 8) * ldr + base + cb;
        __nv_bfloat16 h0,h1,h2,h3,l0,l1,l2,l3;
        split2(O[nt][0] * inv0, h0, l0);
        split2(O[nt][1] * inv0, h1, l1);
        split2(O[nt][2] * inv1, h2, l2);
        split2(O[nt][3] * inv1, h3, l3);
        *(uint32_t*)(Oh_g + o0) = pack2(h0, h1);
        *(uint32_t*)(Ol_g + o0) = pack2(l0, l1);
        *(uint32_t*)(Oh_g + o1) = pack2(h2, h3);
        *(uint32_t*)(Ol_g + o1) = pack2(l2, l3);
    }
}

// ================= HMMA GEMM: 64x128 CTA tile, 8 warps (2x4), KC=32 =================
// Doubled grid vs 128x128 -> every SM holds >=2 CTAs; smaller smem/regs.
#define KC 32
#define PA 40
#define TA_E (64 * PA)                 // A tile elems (per h/l)
#define TB_E (128 * PA)                // B tile elems (per h/l)
#define BUF_E (2 * TA_E + 2 * TB_E)    // 15360 elems per buffer
#define GEMM_SMEM (2 * BUF_E * 2)      // 61440 B

__device__ __forceinline__
void gemm_body(__nv_bfloat16* sm,
               const __nv_bfloat16* __restrict__ Ah, const __nv_bfloat16* __restrict__ Al,
               const __nv_bfloat16* __restrict__ Bh, const __nv_bfloat16* __restrict__ Bl,
               const float* __restrict__ bias, const float* __restrict__ residual,
               float* __restrict__ Cf,
               __nv_bfloat16* __restrict__ Ch, __nv_bfloat16* __restrict__ Cl,
               int K, int lda, int ldb, int ldc, int relu)
{
    const int tid = threadIdx.x;
    const int lane = tid & 31;
    const int wid = tid >> 5;
    const int warpM = wid & 1;         // 0..1 -> 32-row half
    const int warpN = wid >> 1;        // 0..3 -> 32-col quarter
    const int rowBase = blockIdx.y * 64;
    const int colBase = blockIdx.x * 128;

    // A loader: 64 rows x 32 k; 1 CP16 per h/l array per thread
    const int ar = tid >> 2;           // 0..63
    const int akq = (tid & 3) << 3;    // 0,8,16,24
    // B loader: 128 rows x 32 k; 2 CP16 per h/l array per thread
    const int br = tid >> 1;           // 0..127
    const int bhf = (tid & 1) << 4;    // 0 or 16

    auto issue = [&](int k0, int buf) {
        __nv_bfloat16* base_p = sm + buf * BUF_E;
        const long aoff = (long)(rowBase + ar) * lda + k0 + akq;
        const long boff = (long)(colBase + br) * ldb + k0 + bhf;
        const uint32_t da = smaddr(&base_p[ar * PA + akq]);
        const uint32_t db = smaddr(&base_p[2 * TA_E + br * PA + bhf]);
        CP16(da,                 Ah + aoff);
        CP16(da + TA_E * 2,      Al + aoff);
        CP16(db,                 Bh + boff);
        CP16(db + 16,            Bh + boff + 8);
        CP16(db + TB_E * 2,      Bl + boff);
        CP16(db + TB_E * 2 + 16, Bl + boff + 8);
        CP_COMMIT();
    };

    float acc[2][4][4];
#pragma unroll
    for (int i = 0; i < 2; i++)
#pragma unroll
        for (int j = 0; j < 4; j++)
#pragma unroll
            for (int rr = 0; rr < 4; rr++) acc[i][j][rr] = 0.f;

    const int NC = K / KC;
    issue(0, 0);
    CP_WAIT0();
    __syncthreads();

    int buf = 0;
    for (int c = 0; c < NC; c++) {
        const bool has = (c + 1) < NC;
        if (has) issue((c + 1) * KC, buf ^ 1);

        const __nv_bfloat16* pAh = sm + buf * BUF_E;
        const __nv_bfloat16* pAl = pAh + TA_E;
        const __nv_bfloat16* pBh = pAh + 2 * TA_E;
        const __nv_bfloat16* pBl = pBh + TB_E;
        const int rql = lane >> 2;
        const int kof = (lane & 3) << 1;

#pragma unroll
        for (int ks = 0; ks < KC; ks += 16) {
            const int kcol = ks + kof;
            uint32_t bh[4][2], bl[4][2];
#pragma unroll
            for (int nt = 0; nt < 4; nt++) {
                const int n0 = warpN * 32 + nt * 8 + rql;
                bh[nt][0] = *(const uint32_t*)&pBh[n0 * PA + kcol];
                bh[nt][1] = *(const uint32_t*)&pBh[n0 * PA + kcol + 8];
                bl[nt][0] = *(const uint32_t*)&pBl[n0 * PA + kcol];
                bl[nt][1] = *(const uint32_t*)&pBl[n0 * PA + kcol + 8];
            }
            uint32_t ah[2][4], al[2][4];
#pragma unroll
            for (int mt = 0; mt < 2; mt++) {
                const int r0 = warpM * 32 + mt * 16 + rql;
                ah[mt][0] = *(const uint32_t*)&pAh[r0 * PA + kcol];
                ah[mt][1] = *(const uint32_t*)&pAh[(r0 + 8) * PA + kcol];
                ah[mt][2] = *(const uint32_t*)&pAh[r0 * PA + kcol + 8];
                ah[mt][3] = *(const uint32_t*)&pAh[(r0 + 8) * PA + kcol + 8];
                al[mt][0] = *(const uint32_t*)&pAl[r0 * PA + kcol];
                al[mt][1] = *(const uint32_t*)&pAl[(r0 + 8) * PA + kcol];
                al[mt][2] = *(const uint32_t*)&pAl[r0 * PA + kcol + 8];
                al[mt][3] = *(const uint32_t*)&pAl[(r0 + 8) * PA + kcol + 8];
            }
            // term-major: 8 independent MMAs between accumulator reuses
#pragma unroll
            for (int mt = 0; mt < 2; mt++)
#pragma unroll
                for (int nt = 0; nt < 4; nt++)
                    mma16816(acc[mt][nt], ah[mt], bh[nt]);
#pragma unroll
            for (int mt = 0; mt < 2; mt++)
#pragma unroll
                for (int nt = 0; nt < 4; nt++)
                    mma16816(acc[mt][nt], al[mt], bh[nt]);
#pragma unroll
            for (int mt = 0; mt < 2; mt++)
#pragma unroll
                for (int nt = 0; nt < 4; nt++)
                    mma16816(acc[mt][nt], ah[mt], bl[nt]);
        }

        if (has) CP_WAIT0();
        __syncthreads();
        buf ^= 1;
    }

    const int rql = lane >> 2;
    const int cof = (lane & 3) << 1;
#pragma unroll
    for (int mt = 0; mt < 2; mt++) {
        const int r0 = rowBase + warpM * 32 + mt * 16 + rql;
#pragma unroll
        for (int nt = 0; nt < 4; nt++) {
            const int cb = colBase + warpN * 32 + nt * 8 + cof;
            float* a4 = acc[mt][nt];
            float2 bb = make_float2(0.f, 0.f);
            if (bias) bb = *(const float2*)(bias + cb);
            float v0 = a4[0] + bb.x;
            float v1 = a4[1] + bb.y;
            float v2 = a4[2] + bb.x;
            float v3 = a4[3] + bb.y;
            if (relu) {
                v0 = fmaxf(v0, 0.f); v1 = fmaxf(v1, 0.f);
                v2 = fmaxf(v2, 0.f); v3 = fmaxf(v3, 0.f);
            }
            const long o0 = (long)r0 * ldc + cb;
            const long o1 = (long)(r0 + 8) * ldc + cb;
            if (residual) {
                float2 r00 = *(const float2*)(residual + o0);
                float2 r11 = *(const float2*)(residual + o1);
                v0 += r00.x; v1 += r00.y; v2 += r11.x; v3 += r11.y;
            }
            if (Cf) {
                *(float2*)(Cf + o0) = make_float2(v0, v1);
                *(float2*)(Cf + o1) = make_float2(v2, v3);
            }
            if (Ch) {
                __nv_bfloat16 h0,h1,h2,h3,l0,l1,l2,l3;
                split2(v0, h0, l0); split2(v1, h1, l1);
                split2(v2, h2, l2); split2(v3, h3, l3);
                *(uint32_t*)(Ch + o0) = pack2(h0, h1);
                *(uint32_t*)(Cl + o0) = pack2(l0, l1);
                *(uint32_t*)(Ch + o1) = pack2(h2, h3);
                *(uint32_t*)(Cl + o1) = pack2(l2, l3);
            }
        }
    }
}

__global__ __launch_bounds__(256, 2)
void gemm_hmma(const __nv_bfloat16* Ah, const __nv_bfloat16* Al,
               const __nv_bfloat16* Bh, const __nv_bfloat16* Bl,
               const float* bias, const float* residual,
               float* Cf, __nv_bfloat16* Ch, __nv_bfloat16* Cl,
               int K, int lda, int ldb, int ldc, int relu)
{
    extern __shared__ char dsm[];
    gemm_body((__nv_bfloat16*)dsm, Ah, Al, Bh, Bl, bias, residual,
              Cf, Ch, Cl, K, lda, ldb, ldc, relu);
}

// fused QKV: blockIdx.z selects weight/bias/output; emits split outputs
__global__ __launch_bounds__(256, 2)
void gemm_qkv(const __nv_bfloat16* xh, const __nv_bfloat16* xl,
              const __nv_bfloat16* w0h, const __nv_bfloat16* w0l,
              const __nv_bfloat16* w1h, const __nv_bfloat16* w1l,
              const __nv_bfloat16* w2h, const __nv_bfloat16* w2l,
              const float* b0, const float* b1, const float* b2,
              __nv_bfloat16* c0h, __nv_bfloat16* c0l,
              __nv_bfloat16* c1h, __nv_bfloat16* c1l,
              __nv_bfloat16* c2h, __nv_bfloat16* c2l)
{
    extern __shared__ char dsm[];
    const int z = blockIdx.z;
    const __nv_bfloat16* Bh = (z == 0) ? w0h : (z == 1) ? w1h : w2h;
    const __nv_bfloat16* Bl = (z == 0) ? w0l : (z == 1) ? w1l : w2l;
    const float* bias = (z == 0) ? b0 : (z == 1) ? b1 : b2;
    __nv_bfloat16* Ch = (z == 0) ? c0h : (z == 1) ? c1h : c2h;
    __nv_bfloat16* Cl = (z == 0) ? c0l : (z == 1) ? c1l : c2l;
    gemm_body((__nv_bfloat16*)dsm, xh, xl, Bh, Bl, bias, nullptr,
              nullptr, Ch, Cl, D_, D_, D_, D_, 0);
}

// ---------------- block reduction ----------------
__device__ __forceinline__ float blockReduceSum(float v) {
    __shared__ float s[8];
#pragma unroll
    for (int o = 16; o > 0; o >>= 1) v += __shfl_xor_sync(0xffffffffu, v, o);
    int w = threadIdx.x >> 5, l = threadIdx.x & 31;
    if (l == 0) s[w] = v;
    __syncthreads();
    if (threadIdx.x < 32) {
        v = (threadIdx.x < 8) ? s[threadIdx.x] : 0.f;
#pragma unroll
        for (int o = 4; o > 0; o >>= 1) v += __shfl_xor_sync(0xffffffffu, v, o);
        if (threadIdx.x == 0) s[0] = v;
    }
    __syncthreads();
    v = s[0];
    __syncthreads();
    return v;
}

// ---------------- layernorm (optional split emit) ----------------
__global__ void layernorm_kernel(const float* __restrict__ X,
                                 const float* __restrict__ g,
                                 const float* __restrict__ b,
                                 float* __restrict__ Y,
                                 __nv_bfloat16* __restrict__ Yh,
                                 __nv_bfloat16* __restrict__ Yl) {
    long row = blockIdx.x;
    const float* p = X + row * D_;
    int tid = threadIdx.x;
    float vals[3];
    float sum = 0.f;
#pragma unroll
    for (int i = 0; i < 3; i++) {
        vals[i] = p[tid + i * 256];
        sum += vals[i];
    }
    float mu = blockReduceSum(sum) * (1.f / D_);
    float vs = 0.f;
#pragma unroll
    for (int i = 0; i < 3; i++) {
        float d = vals[i] - mu;
        vs += d * d;
    }
    float var = blockReduceSum(vs) * (1.f / D_);
    float rs = rsqrtf(var + 1e-5f);
#pragma unroll
    for (int i = 0; i < 3; i++) {
        int c = tid + i * 256;
        float o = (vals[i] - mu) * rs * g[c] + b[c];
        if (Y) Y[row * D_ + c] = o;
        if (Yh) {
            __nv_bfloat16 h, l;
            split2(o, h, l);
            Yh[row * D_ + c] = h;
            Yl[row * D_ + c] = l;
        }
    }
}

// ---------------- launch ----------------
extern "C" void kernel_launch(void* const* d_in, const int* in_sizes, int n_in,
                              void* d_out, int out_size)
{
    const float* x     = (const float*)d_in[0];
    const float* wq    = (const float*)d_in[1];
    const float* bq    = (const float*)d_in[2];
    const float* wk    = (const float*)d_in[3];
    const float* bk    = (const float*)d_in[4];
    const float* wv    = (const float*)d_in[5];
    const float* bv    = (const float*)d_in[6];
    const float* wo    = (const float*)d_in[7];
    const float* bo    = (const float*)d_in[8];
    const float* ln1g  = (const float*)d_in[9];
    const float* ln1b  = (const float*)d_in[10];
    const float* w1    = (const float*)d_in[11];
    const float* b1    = (const float*)d_in[12];
    const float* w2    = (const float*)d_in[13];
    const float* b2    = (const float*)d_in[14];
    const float* ln2g  = (const float*)d_in[15];
    const float* ln2b  = (const float*)d_in[16];
    float* out = (float*)d_out;

    float *tmp1, *x1, *y;
    cudaGetSymbolAddress((void**)&tmp1, g_tmp1);
    cudaGetSymbolAddress((void**)&x1,   g_x1);
    cudaGetSymbolAddress((void**)&y,    g_y);

    __nv_bfloat16 *xh,*xl,*qh,*ql,*kh,*kl,*vh,*vl,*ah,*al,*x1h,*x1l,*h1h,*h1l;
    __nv_bfloat16 *wqh,*wql,*wkh,*wkl,*wvh,*wvl,*woh,*wol,*w1h,*w1l,*w2h,*w2l;
    cudaGetSymbolAddress((void**)&xh, g_xh);   cudaGetSymbolAddress((void**)&xl, g_xl);
    cudaGetSymbolAddress((void**)&qh, g_qh);   cudaGetSymbolAddress((void**)&ql, g_ql);
    cudaGetSymbolAddress((void**)&kh, g_kh);   cudaGetSymbolAddress((void**)&kl, g_kl);
    cudaGetSymbolAddress((void**)&vh, g_vh);   cudaGetSymbolAddress((void**)&vl, g_vl);
    cudaGetSymbolAddress((void**)&ah, g_ah);   cudaGetSymbolAddress((void**)&al, g_al);
    cudaGetSymbolAddress((void**)&x1h, g_x1h); cudaGetSymbolAddress((void**)&x1l, g_x1l);
    cudaGetSymbolAddress((void**)&h1h, g_h1h); cudaGetSymbolAddress((void**)&h1l, g_h1l);
    cudaGetSymbolAddress((void**)&wqh, g_wqh); cudaGetSymbolAddress((void**)&wql, g_wql);
    cudaGetSymbolAddress((void**)&wkh, g_wkh); cudaGetSymbolAddress((void**)&wkl, g_wkl);
    cudaGetSymbolAddress((void**)&wvh, g_wvh); cudaGetSymbolAddress((void**)&wvl, g_wvl);
    cudaGetSymbolAddress((void**)&woh, g_woh); cudaGetSymbolAddress((void**)&wol, g_wol);
    cudaGetSymbolAddress((void**)&w1h, g_w1h); cudaGetSymbolAddress((void**)&w1l, g_w1l);
    cudaGetSymbolAddress((void**)&w2h, g_w2h); cudaGetSymbolAddress((void**)&w2l, g_w2l);

    cudaFuncSetAttribute(gemm_hmma, cudaFuncAttributeMaxDynamicSharedMemorySize, GEMM_SMEM);
    cudaFuncSetAttribute(gemm_qkv,  cudaFuncAttributeMaxDynamicSharedMemorySize, GEMM_SMEM);
    cudaFuncSetAttribute(flash_attn, cudaFuncAttributeMaxDynamicSharedMemorySize, FLASH_SMEM);

    const float scale2 = 0.102062072615966f * 1.44269504088896f;
    dim3 blk(256);

    // ---- one-time splits (x + all weights, single launch)
    split_all<<<SPLIT_BLOCKS, blk>>>(x, wq, wk, wv, wo, w1, w2,
                                     xh, xl, wqh, wql, wkh, wkl, wvh, wvl,
                                     woh, wol, w1h, w1l, w2h, w2l);

    // ---- QKV projections (fused; split outputs feed flash)
    dim3 gQKV(D_ / 128, NR_ / 64, 3);
    gemm_qkv<<<gQKV, blk, GEMM_SMEM>>>(xh, xl, wqh, wql, wkh, wkl, wvh, wvl,
                                       bq, bk, bv, qh, ql, kh, kl, vh, vl);

    // ---- flash attention (split in, split out)
    dim3 gFA(T_ / 64, BH_);
    flash_attn<<<gFA, dim3(128), FLASH_SMEM>>>(qh, ql, kh, kl, vh, vl, ah, al, scale2);

    // ---- O projection + residual(x) -> tmp1 (fp32)
    dim3 gProj(D_ / 128, NR_ / 64);
    gemm_hmma<<<gProj, blk, GEMM_SMEM>>>(ah, al, woh, wol, bo, x,
                                         tmp1, nullptr, nullptr, D_, D_, D_, D_, 0);

    // ---- LN1 -> x1 fp32 + split
    layernorm_kernel<<<NR_, blk>>>(tmp1, ln1g, ln1b, x1, x1h, x1l);

    // ---- FFN1: relu -> h1 split only
    dim3 gF1(FFN_ / 128, NR_ / 64);
    gemm_hmma<<<gF1, blk, GEMM_SMEM>>>(x1h, x1l, w1h, w1l, b1, nullptr,
                                       nullptr, h1h, h1l, D_, D_, D_, FFN_, 1);

    // ---- FFN2 + residual(x1) -> y fp32
    gemm_hmma<<<gProj, blk, GEMM_SMEM>>>(h1h, h1l, w2h, w2l, b2, x1,
                                         y, nullptr, nullptr, FFN_, FFN_, FFN_, D_, 0);

    // ---- LN2 -> out
    layernorm_kernel<<<NR_, blk>>>(y, ln2g, ln2b, out, nullptr, nullptr);
}